// round 7
// baseline (speedup 1.0000x reference)
#include <cuda_runtime.h>

typedef unsigned long long ull;

#define BATCH 4096

// ---------------- device scratch (no allocations allowed) ----------------
__device__ float g_h  [BATCH * 512];
__device__ float g_qx [BATCH * 512];
__device__ float g_qW2[512 * 512];
__device__ float g_h2 [BATCH * 512];
__device__ float g_qx2[BATCH * 512];
__device__ double g_bnsum[512];
__device__ double g_bnsq [512];
__device__ double g_dsum[3];   // [0]=fq21 sum, [1]=wq sum, [2]=fq22 sum

// ---------------- packed f32x2 helpers (Blackwell FFMA2) ----------------
__device__ __forceinline__ ull pack2(float x, float y) {
    ull r;
    unsigned xu = __float_as_uint(x), yu = __float_as_uint(y);
    asm("mov.b64 %0, {%1, %2};" : "=l"(r) : "r"(xu), "r"(yu));
    return r;
}
__device__ __forceinline__ float2 unpack2(ull v) {
    unsigned lo, hi;
    asm("mov.b64 {%0, %1}, %2;" : "=r"(lo), "=r"(hi) : "l"(v));
    float2 f; f.x = __uint_as_float(lo); f.y = __uint_as_float(hi);
    return f;
}
__device__ __forceinline__ ull ffma2(ull a, ull b, ull c) {
    ull d;
    asm("fma.rn.f32x2 %0, %1, %2, %3;" : "=l"(d) : "l"(a), "l"(b), "l"(c));
    return d;
}

// ---------------- block reduce -> atomic double ----------------
__device__ __forceinline__ void block_sum_to(double* target, float v) {
    __shared__ float red[8];
    const int tid = threadIdx.x;
    #pragma unroll
    for (int o = 16; o; o >>= 1) v += __shfl_xor_sync(0xffffffffu, v, o);
    if ((tid & 31) == 0) red[tid >> 5] = v;
    __syncthreads();
    if (tid == 0) {
        float s = 0.f;
        const int nw = (blockDim.x + 31) >> 5;
        for (int w = 0; w < nw; w++) s += red[w];
        atomicAdd(target, (double)s);
    }
}

// ---------------- GEMM: C[m,n] = relu( sum_k f(A[m,k]) * W[n,k] ) ----------------
// BM=128, BN=64, BK=16, 64 threads, per-thread 16m x 8n, FFMA2 over m-pairs.
// A read from smem as ulonglong2 (natural packed pairs). Double-buffered,
// ONE barrier per k-tile. AFFINE: A -> A*scale[k]+shift[k] (fused BN).
template<int KDIM, bool AFFINE>
__global__ __launch_bounds__(64, 2)
void gemm_kernel(const float* __restrict__ Aext, const float* __restrict__ Wext,
                 const float* __restrict__ gamma, const float* __restrict__ beta)
{
    const float* __restrict__ A = AFFINE ? (const float*)g_qx  : Aext;
    const float* __restrict__ W = AFFINE ? (const float*)g_qW2 : Wext;
    float*       __restrict__ C = AFFINE ? (float*)g_h2 : (float*)g_h;

    __shared__ __align__(16) float As[2][16][132];
    __shared__ __align__(16) float Bs[2][16][68];
    __shared__ __align__(16) float sScale[AFFINE ? 512 : 4];
    __shared__ __align__(16) float sShift[AFFINE ? 512 : 4];

    const int tid  = threadIdx.x;
    const int tx   = tid & 7;         // n group (8 cols)
    const int ty   = tid >> 3;        // m group (16 rows)
    const int m0   = blockIdx.y * 128;
    const int n0   = blockIdx.x * 64;
    const int lrow = tid >> 1;        // loader row base 0..31
    const int lk   = (tid & 1) * 8;   // loader k half: 0 or 8

    if (AFFINE) {
        for (int c = tid; c < 512; c += 64) {
            float S  = (float)g_bnsum[c];
            float S2 = (float)g_bnsq[c];
            float mu  = S * (1.f / BATCH);
            float var = fmaf(-mu, mu, S2 * (1.f / BATCH));
            float sc  = gamma[c] * rsqrtf(var + 1e-5f);
            sScale[c] = sc;
            sShift[c] = fmaf(-mu, sc, beta[c]);
        }
        __syncthreads();
    } else if (blockIdx.x == 0 && blockIdx.y == 0) {
        // first kernel in the graph: zero all accumulators
        for (int i = tid; i < 512; i += 64) { g_bnsum[i] = 0.0; g_bnsq[i] = 0.0; }
        if (tid < 3) g_dsum[tid] = 0.0;
    }

    constexpr int NT = KDIM / 16;
    float4 pa[8], pb[4];

    // prefetch tile 0: A rows lrow+l*32 (l=0..3), k = lk + f*4 (f=0..1)
    #pragma unroll
    for (int l = 0; l < 4; l++)
        #pragma unroll
        for (int f = 0; f < 2; f++)
            pa[l * 2 + f] = *(const float4*)(A + (size_t)(m0 + lrow + l * 32) * KDIM + lk + f * 4);
    #pragma unroll
    for (int l = 0; l < 2; l++)
        #pragma unroll
        for (int f = 0; f < 2; f++)
            pb[l * 2 + f] = *(const float4*)(W + (size_t)(n0 + lrow + l * 32) * KDIM + lk + f * 4);

    #define STORE_TILE(buf, ktv) do {                                            \
        _Pragma("unroll")                                                        \
        for (int l = 0; l < 4; l++) {                                            \
            _Pragma("unroll")                                                    \
            for (int f = 0; f < 2; f++) {                                        \
                float4 av = pa[l * 2 + f];                                       \
                if (AFFINE) {                                                    \
                    float4 sc = *(const float4*)&sScale[(ktv) * 16 + lk + f * 4];\
                    float4 sh = *(const float4*)&sShift[(ktv) * 16 + lk + f * 4];\
                    av.x = fmaf(av.x, sc.x, sh.x);                               \
                    av.y = fmaf(av.y, sc.y, sh.y);                               \
                    av.z = fmaf(av.z, sc.z, sh.z);                               \
                    av.w = fmaf(av.w, sc.w, sh.w);                               \
                }                                                                \
                As[buf][lk + f * 4 + 0][lrow + l * 32] = av.x;                   \
                As[buf][lk + f * 4 + 1][lrow + l * 32] = av.y;                   \
                As[buf][lk + f * 4 + 2][lrow + l * 32] = av.z;                   \
                As[buf][lk + f * 4 + 3][lrow + l * 32] = av.w;                   \
            }                                                                    \
        }                                                                        \
        _Pragma("unroll")                                                        \
        for (int l = 0; l < 2; l++) {                                            \
            _Pragma("unroll")                                                    \
            for (int f = 0; f < 2; f++) {                                        \
                float4 bv = pb[l * 2 + f];                                       \
                Bs[buf][lk + f * 4 + 0][lrow + l * 32] = bv.x;                   \
                Bs[buf][lk + f * 4 + 1][lrow + l * 32] = bv.y;                   \
                Bs[buf][lk + f * 4 + 2][lrow + l * 32] = bv.z;                   \
                Bs[buf][lk + f * 4 + 3][lrow + l * 32] = bv.w;                   \
            }                                                                    \
        }                                                                        \
    } while (0)

    STORE_TILE(0, 0);
    __syncthreads();

    ull acc[8][8];
    #pragma unroll
    for (int p = 0; p < 8; p++)
        #pragma unroll
        for (int n = 0; n < 8; n++) acc[p][n] = 0ull;

    for (int kt = 0; kt < NT; kt++) {
        const int cur = kt & 1;
        if (kt + 1 < NT) {
            #pragma unroll
            for (int l = 0; l < 4; l++)
                #pragma unroll
                for (int f = 0; f < 2; f++)
                    pa[l * 2 + f] = *(const float4*)(A + (size_t)(m0 + lrow + l * 32) * KDIM
                                                     + (kt + 1) * 16 + lk + f * 4);
            #pragma unroll
            for (int l = 0; l < 2; l++)
                #pragma unroll
                for (int f = 0; f < 2; f++)
                    pb[l * 2 + f] = *(const float4*)(W + (size_t)(n0 + lrow + l * 32) * KDIM
                                                     + (kt + 1) * 16 + lk + f * 4);
        }
        #pragma unroll
        for (int k = 0; k < 16; k++) {
            // A: 16 m-values = 8 natural ull pairs, four 128-bit loads, no packing
            const ulonglong2 A01 = *(const ulonglong2*)&As[cur][k][ty * 16];
            const ulonglong2 A23 = *(const ulonglong2*)&As[cur][k][ty * 16 + 4];
            const ulonglong2 A45 = *(const ulonglong2*)&As[cur][k][ty * 16 + 8];
            const ulonglong2 A67 = *(const ulonglong2*)&As[cur][k][ty * 16 + 12];
            const float4 b0 = *(const float4*)&Bs[cur][k][tx * 8];
            const float4 b1 = *(const float4*)&Bs[cur][k][tx * 8 + 4];
            ull ap[8] = { A01.x, A01.y, A23.x, A23.y, A45.x, A45.y, A67.x, A67.y };
            float bv[8] = { b0.x, b0.y, b0.z, b0.w, b1.x, b1.y, b1.z, b1.w };
            #pragma unroll
            for (int n = 0; n < 8; n++) {
                ull bb = pack2(bv[n], bv[n]);
                #pragma unroll
                for (int p = 0; p < 8; p++)
                    acc[p][n] = ffma2(ap[p], bb, acc[p][n]);
            }
        }
        if (kt + 1 < NT) {
            // safe with ONE barrier: this iteration read `cur` only; `cur^1`'s
            // last readers (iteration kt-1) all passed the previous barrier.
            STORE_TILE(cur ^ 1, kt + 1);
            __syncthreads();
        }
    }
    #undef STORE_TILE

    // epilogue: relu + store (rows come in m-pairs)
    #pragma unroll
    for (int p = 0; p < 8; p++) {
        const int r0 = m0 + ty * 16 + 2 * p;
        float v0[8], v1[8];
        #pragma unroll
        for (int n = 0; n < 8; n++) {
            float2 f = unpack2(acc[p][n]);
            v0[n] = fmaxf(f.x, 0.f);
            v1[n] = fmaxf(f.y, 0.f);
        }
        *(float4*)(C + (size_t)r0 * 512 + n0 + tx * 8)           = make_float4(v0[0], v0[1], v0[2], v0[3]);
        *(float4*)(C + (size_t)r0 * 512 + n0 + tx * 8 + 4)       = make_float4(v0[4], v0[5], v0[6], v0[7]);
        *(float4*)(C + (size_t)(r0 + 1) * 512 + n0 + tx * 8)     = make_float4(v1[0], v1[1], v1[2], v1[3]);
        *(float4*)(C + (size_t)(r0 + 1) * 512 + n0 + tx * 8 + 4) = make_float4(v1[4], v1[5], v1[6], v1[7]);
    }
}

// ---------------- fq21: dim-8 VQ of h (strided groups) + fused BN stats ----------------
// vector (b,c): v_j = h[b, j*64+c].  4 vectors/thread, 4-code groups, group-min + index recovery.
__global__ __launch_bounds__(256, 2)
void fq21_kernel(const float* __restrict__ E)   // E: [8,512]
{
    __shared__ __align__(16) float sE[8][512];
    __shared__ __align__(16) float sC2[512];
    __shared__ float sBS[4][512];   // per-quadrant column sums
    __shared__ float sBQ[4][512];   // per-quadrant column sq-sums
    const int tid = threadIdx.x;
    for (int i = tid; i < 8 * 512; i += 256) ((float*)sE)[i] = E[i];
    __syncthreads();
    for (int e = tid; e < 512; e += 256) {
        float s = 0.f;
        #pragma unroll
        for (int j = 0; j < 8; j++) s = fmaf(sE[j][e], sE[j][e], s);
        sC2[e] = s;
    }
    __syncthreads();

    const int base = blockIdx.x * 1024 + tid;
    ull vr[4][8];
    #pragma unroll
    for (int s = 0; s < 4; s++) {
        const int vid = base + s * 256;
        const int b = vid >> 6, c = vid & 63;
        #pragma unroll
        for (int j = 0; j < 8; j++) {
            float v = g_h[(size_t)b * 512 + j * 64 + c];
            vr[s][j] = pack2(v, v);
        }
    }

    float bestd[4] = {1e30f, 1e30f, 1e30f, 1e30f};
    int   bg[4]    = {0, 0, 0, 0};
    const ull M2 = pack2(-2.f, -2.f);

    #pragma unroll 2
    for (int u = 0; u < 128; u++) {
        const ull c2A = *(const ull*)&sC2[4 * u];
        const ull c2B = *(const ull*)&sC2[4 * u + 2];
        ull a[4], b2[4];
        {
            const ull eA = *(const ull*)&sE[0][4 * u];
            const ull eB = *(const ull*)&sE[0][4 * u + 2];
            #pragma unroll
            for (int s = 0; s < 4; s++) {
                a [s] = ffma2(vr[s][0], eA, 0ull);
                b2[s] = ffma2(vr[s][0], eB, 0ull);
            }
        }
        #pragma unroll
        for (int j = 1; j < 8; j++) {
            const ull eA = *(const ull*)&sE[j][4 * u];
            const ull eB = *(const ull*)&sE[j][4 * u + 2];
            #pragma unroll
            for (int s = 0; s < 4; s++) {
                a [s] = ffma2(vr[s][j], eA, a [s]);
                b2[s] = ffma2(vr[s][j], eB, b2[s]);
            }
        }
        #pragma unroll
        for (int s = 0; s < 4; s++) {
            float2 fa = unpack2(ffma2(M2, a [s], c2A));
            float2 fb = unpack2(ffma2(M2, b2[s], c2B));
            float m = fminf(fminf(fa.x, fa.y), fminf(fb.x, fb.y));
            if (m < bestd[s]) { bestd[s] = m; bg[s] = u; }
        }
    }

    // index recovery + straight-through write + BN private accumulation
    float priv_s[8], priv_q[8];
    #pragma unroll
    for (int j = 0; j < 8; j++) { priv_s[j] = 0.f; priv_q[j] = 0.f; }
    float lsum = 0.f;
    #pragma unroll
    for (int s = 0; s < 4; s++) {
        const int u = bg[s];
        ull a = 0ull, b2 = 0ull;
        #pragma unroll
        for (int j = 0; j < 8; j++) {
            a  = ffma2(vr[s][j], *(const ull*)&sE[j][4 * u],     a);
            b2 = ffma2(vr[s][j], *(const ull*)&sE[j][4 * u + 2], b2);
        }
        float2 fa = unpack2(ffma2(M2, a,  *(const ull*)&sC2[4 * u]));
        float2 fb = unpack2(ffma2(M2, b2, *(const ull*)&sC2[4 * u + 2]));
        int e = 4 * u;
        if      (fa.x == bestd[s]) e += 0;
        else if (fa.y == bestd[s]) e += 1;
        else if (fb.x == bestd[s]) e += 2;
        else                       e += 3;

        const int vid = base + s * 256;
        const int b = vid >> 6, c = vid & 63;
        #pragma unroll
        for (int j = 0; j < 8; j++) {
            float v  = unpack2(vr[s][j]).x;
            float dq = sE[j][e] - v;
            lsum = fmaf(dq, dq, lsum);
            float qst = v + dq;                      // straight-through value
            g_qx[(size_t)b * 512 + j * 64 + c] = qst;
            priv_s[j] += qst;
            priv_q[j]  = fmaf(qst, qst, priv_q[j]);
        }
    }

    // BN slab reduce: column = j*64 + (tid&63); quadrant q = tid>>6
    {
        const int q = tid >> 6, c = tid & 63;
        #pragma unroll
        for (int j = 0; j < 8; j++) {
            sBS[q][j * 64 + c] = priv_s[j];
            sBQ[q][j * 64 + c] = priv_q[j];
        }
    }
    __syncthreads();
    for (int cell = tid; cell < 512; cell += 256) {
        float s  = sBS[0][cell] + sBS[1][cell] + sBS[2][cell] + sBS[3][cell];
        float s2 = sBQ[0][cell] + sBQ[1][cell] + sBQ[2][cell] + sBQ[3][cell];
        atomicAdd(&g_bnsum[cell], (double)s);
        atomicAdd(&g_bnsq [cell], (double)s2);
    }
    block_sum_to(&g_dsum[0], lsum);
}

// ---------------- weight VQ of W2 (dim-16 groups), 4 threads per vector ----------------
__global__ __launch_bounds__(256)
void wq_kernel(const float* __restrict__ W2, const float* __restrict__ E)
{
    __shared__ __align__(16) float sE[16][512];
    __shared__ __align__(16) float sC2[512];
    const int tid = threadIdx.x;
    for (int i = tid; i < 16 * 512; i += 256) ((float*)sE)[i] = E[i];
    __syncthreads();
    for (int e = tid; e < 512; e += 256) {
        float s = 0.f;
        #pragma unroll
        for (int k = 0; k < 16; k++) s = fmaf(sE[k][e], sE[k][e], s);
        sC2[e] = s;
    }
    __syncthreads();

    const int vec   = blockIdx.x * 64 + (tid >> 2);   // 0..16383
    const int slice = tid & 3;
    const int g = vec >> 6, c = vec & 63;

    ull vr[16];
    #pragma unroll
    for (int k = 0; k < 16; k++) {
        float v = W2[(size_t)(g * 2 + (k & 1)) * 512 + c * 8 + (k >> 1)];
        vr[k] = pack2(v, v);
    }

    float bestd = 1e30f; int bg = slice;
    const ull M2 = pack2(-2.f, -2.f);
    #pragma unroll 2
    for (int uu = 0; uu < 32; uu++) {
        const int u = 4 * uu + slice;
        ull a = 0ull, b2 = 0ull;
        #pragma unroll
        for (int k = 0; k < 16; k++) {
            a  = ffma2(vr[k], *(const ull*)&sE[k][4 * u],     a);
            b2 = ffma2(vr[k], *(const ull*)&sE[k][4 * u + 2], b2);
        }
        float2 fa = unpack2(ffma2(M2, a,  *(const ull*)&sC2[4 * u]));
        float2 fb = unpack2(ffma2(M2, b2, *(const ull*)&sC2[4 * u + 2]));
        float m = fminf(fminf(fa.x, fa.y), fminf(fb.x, fb.y));
        if (m < bestd) { bestd = m; bg = u; }
    }
    int idx;
    {
        ull a = 0ull, b2 = 0ull;
        #pragma unroll
        for (int k = 0; k < 16; k++) {
            a  = ffma2(vr[k], *(const ull*)&sE[k][4 * bg],     a);
            b2 = ffma2(vr[k], *(const ull*)&sE[k][4 * bg + 2], b2);
        }
        float2 fa = unpack2(ffma2(M2, a,  *(const ull*)&sC2[4 * bg]));
        float2 fb = unpack2(ffma2(M2, b2, *(const ull*)&sC2[4 * bg + 2]));
        idx = 4 * bg;
        if      (fa.x == bestd) idx += 0;
        else if (fa.y == bestd) idx += 1;
        else if (fb.x == bestd) idx += 2;
        else                    idx += 3;
    }
    #pragma unroll
    for (int off = 1; off < 4; off <<= 1) {
        float od = __shfl_xor_sync(0xffffffffu, bestd, off);
        int   oi = __shfl_xor_sync(0xffffffffu, idx,   off);
        if (od < bestd || (od == bestd && oi < idx)) { bestd = od; idx = oi; }
    }
    #pragma unroll
    for (int kk = 0; kk < 4; kk++) {
        int k = slice * 4 + kk;
        float v  = unpack2(vr[k]).x;
        float dq = sE[k][idx] - v;
        g_qW2[(size_t)(g * 2 + (k & 1)) * 512 + c * 8 + (k >> 1)] = v + dq;
    }
    float lsum = 0.f;
    if (slice == 0) {
        #pragma unroll
        for (int k = 0; k < 16; k++) {
            float v  = unpack2(vr[k]).x;
            float dq = sE[k][idx] - v;
            lsum = fmaf(dq, dq, lsum);
        }
    }
    block_sum_to(&g_dsum[1], lsum);
}

// ---------------- fq22: dim-2 VQ of h2 ----------------
__global__ __launch_bounds__(256)
void fq22_kernel(const float* __restrict__ E)   // E: [2,512]
{
    __shared__ __align__(16) float sm0[512];
    __shared__ __align__(16) float sm1[512];
    __shared__ __align__(16) float sc2[512];
    const int tid = threadIdx.x;
    for (int e = tid; e < 512; e += 256) {
        float e0 = E[e], e1 = E[512 + e];
        sm0[e] = -2.f * e0;
        sm1[e] = -2.f * e1;
        sc2[e] = fmaf(e0, e0, e1 * e1);
    }
    __syncthreads();

    const int base = blockIdx.x * 1024 + tid;
    ull v0r[4], v1r[4];
    #pragma unroll
    for (int s = 0; s < 4; s++) {
        const int vid = base + s * 256;
        const int b = vid >> 8, c = vid & 255;
        float a0 = g_h2[(size_t)b * 512 + c];
        float a1 = g_h2[(size_t)b * 512 + 256 + c];
        v0r[s] = pack2(a0, a0);
        v1r[s] = pack2(a1, a1);
    }
    float bestd[4] = {1e30f, 1e30f, 1e30f, 1e30f};
    int   bg[4]    = {0, 0, 0, 0};
    #pragma unroll 2
    for (int u = 0; u < 128; u++) {
        const ull m0A = *(const ull*)&sm0[4 * u];
        const ull m0B = *(const ull*)&sm0[4 * u + 2];
        const ull m1A = *(const ull*)&sm1[4 * u];
        const ull m1B = *(const ull*)&sm1[4 * u + 2];
        const ull c2A = *(const ull*)&sc2[4 * u];
        const ull c2B = *(const ull*)&sc2[4 * u + 2];
        #pragma unroll
        for (int s = 0; s < 4; s++) {
            float2 fa = unpack2(ffma2(v0r[s], m0A, ffma2(v1r[s], m1A, c2A)));
            float2 fb = unpack2(ffma2(v0r[s], m0B, ffma2(v1r[s], m1B, c2B)));
            float m = fminf(fminf(fa.x, fa.y), fminf(fb.x, fb.y));
            if (m < bestd[s]) { bestd[s] = m; bg[s] = u; }
        }
    }
    float lsum = 0.f;
    #pragma unroll
    for (int s = 0; s < 4; s++) {
        const int u = bg[s];
        float2 fa = unpack2(ffma2(v0r[s], *(const ull*)&sm0[4 * u],
                      ffma2(v1r[s], *(const ull*)&sm1[4 * u], *(const ull*)&sc2[4 * u])));
        float2 fb = unpack2(ffma2(v0r[s], *(const ull*)&sm0[4 * u + 2],
                      ffma2(v1r[s], *(const ull*)&sm1[4 * u + 2], *(const ull*)&sc2[4 * u + 2])));
        int e = 4 * u;
        if      (fa.x == bestd[s]) e += 0;
        else if (fa.y == bestd[s]) e += 1;
        else if (fb.x == bestd[s]) e += 2;
        else                       e += 3;

        const int vid = base + s * 256;
        const int b = vid >> 8, c = vid & 255;
        float e0 = -0.5f * sm0[e];     // exact recovery of codeword
        float e1 = -0.5f * sm1[e];
        float v0 = unpack2(v0r[s]).x;
        float v1 = unpack2(v1r[s]).x;
        float d0 = e0 - v0, d1 = e1 - v1;
        lsum = fmaf(d0, d0, lsum);
        lsum = fmaf(d1, d1, lsum);
        g_qx2[(size_t)b * 512 + c]       = v0 + d0;
        g_qx2[(size_t)b * 512 + 256 + c] = v1 + d1;
    }
    block_sum_to(&g_dsum[2], lsum);
}

// ---------------- final: out = qx2 @ W3^T, plus diff scalar ----------------
__global__ __launch_bounds__(256)
void out_kernel(const float* __restrict__ W3, float* __restrict__ out, int out_size)
{
    __shared__ float sW3[10 * 512];
    const int tid = threadIdx.x;
    for (int i = tid; i < 5120; i += 256) sW3[i] = W3[i];
    __syncthreads();
    const int lane = tid & 31, warp = tid >> 5;
    const int b = blockIdx.x * 8 + warp;
    float p[10];
    #pragma unroll
    for (int k = 0; k < 10; k++) p[k] = 0.f;
    #pragma unroll
    for (int t = 0; t < 16; t++) {
        const int c = t * 32 + lane;
        float v = g_qx2[(size_t)b * 512 + c];
        #pragma unroll
        for (int k = 0; k < 10; k++) p[k] = fmaf(v, sW3[k * 512 + c], p[k]);
    }
    #pragma unroll
    for (int k = 0; k < 10; k++) {
        #pragma unroll
        for (int o = 16; o; o >>= 1) p[k] += __shfl_xor_sync(0xffffffffu, p[k], o);
    }
    if (lane == 0) {
        #pragma unroll
        for (int k = 0; k < 10; k++) out[b * 10 + k] = p[k];
    }
    if (blockIdx.x == 0 && tid == 0 && out_size > BATCH * 10) {
        double diff = g_dsum[0] * (1.0 / 2097152.0)
                    + g_dsum[2] * (1.0 / 2097152.0)
                    + g_dsum[1] * (1.0 / 262144.0);
        out[BATCH * 10] = (float)diff;
    }
}

// ---------------- launch ----------------
extern "C" void kernel_launch(void* const* d_in, const int* in_sizes, int n_in,
                              void* d_out, int out_size)
{
    const float* x      = (const float*)d_in[0];
    const float* W1     = (const float*)d_in[1];
    const float* W2     = (const float*)d_in[2];
    const float* W3     = (const float*)d_in[3];
    const float* gamma1 = (const float*)d_in[4];
    const float* beta1  = (const float*)d_in[5];
    const float* Ef21   = (const float*)d_in[6];
    const float* Eq2    = (const float*)d_in[7];
    const float* Ef22   = (const float*)d_in[8];
    float* out = (float*)d_out;

    gemm_kernel<784, false><<<dim3(8, 32), 64>>>(x, W1, nullptr, nullptr);        // h = relu(x@W1^T)
    fq21_kernel<<<256, 256>>>(Ef21);                                               // h -> qx (+d_f21, +BN)
    wq_kernel<<<256, 256>>>(W2, Eq2);                                              // W2 -> qW2 (+d2)
    gemm_kernel<512, true><<<dim3(8, 32), 64>>>(nullptr, nullptr, gamma1, beta1);  // h2 = relu(bn(qx)@qW2^T)
    fq22_kernel<<<1024, 256>>>(Ef22);                                              // h2 -> qx2 (+d_f22)
    out_kernel<<<512, 256>>>(W3, out, out_size);                                   // logits + diff scalar
}

// round 8
// speedup vs baseline: 1.0158x; 1.0158x over previous
#include <cuda_runtime.h>

typedef unsigned long long ull;

#define BATCH 4096

// ---------------- device scratch (no allocations allowed) ----------------
__device__ float g_h  [BATCH * 512];
__device__ float g_qx [BATCH * 512];
__device__ float g_qW2[512 * 512];
__device__ float g_h2 [BATCH * 512];
__device__ float g_qx2[BATCH * 512];
__device__ double g_bnsum[512];
__device__ double g_bnsq [512];
__device__ double g_dsum[3];   // [0]=fq21 sum, [1]=wq sum, [2]=fq22 sum

// ---------------- packed f32x2 helpers (Blackwell FFMA2) ----------------
__device__ __forceinline__ ull pack2(float x, float y) {
    ull r;
    unsigned xu = __float_as_uint(x), yu = __float_as_uint(y);
    asm("mov.b64 %0, {%1, %2};" : "=l"(r) : "r"(xu), "r"(yu));
    return r;
}
__device__ __forceinline__ float2 unpack2(ull v) {
    unsigned lo, hi;
    asm("mov.b64 {%0, %1}, %2;" : "=r"(lo), "=r"(hi) : "l"(v));
    float2 f; f.x = __uint_as_float(lo); f.y = __uint_as_float(hi);
    return f;
}
__device__ __forceinline__ ull ffma2(ull a, ull b, ull c) {
    ull d;
    asm("fma.rn.f32x2 %0, %1, %2, %3;" : "=l"(d) : "l"(a), "l"(b), "l"(c));
    return d;
}

// ---------------- block reduce -> atomic double ----------------
__device__ __forceinline__ void block_sum_to(double* target, float v) {
    __shared__ float red[8];
    const int tid = threadIdx.x;
    #pragma unroll
    for (int o = 16; o; o >>= 1) v += __shfl_xor_sync(0xffffffffu, v, o);
    if ((tid & 31) == 0) red[tid >> 5] = v;
    __syncthreads();
    if (tid == 0) {
        float s = 0.f;
        const int nw = (blockDim.x + 31) >> 5;
        for (int w = 0; w < nw; w++) s += red[w];
        atomicAdd(target, (double)s);
    }
}

// ---------------- GEMM: C[m,n] = relu( sum_k f(A[m,k]) * W[n,k] ) ----------------
// BM=64, BN=64, BK=16, 128 threads, per-thread 8m x 4n, FFMA2 over m-pairs.
// A read from smem as ulonglong2 (natural packed pairs). Double-buffered,
// ONE barrier per k-tile. occ 4 -> 4 warps/SMSP for latency hiding.
// AFFINE: A -> A*scale[k]+shift[k] (fused BN from g_bnsum/g_bnsq).
template<int KDIM, bool AFFINE>
__global__ __launch_bounds__(128, 4)
void gemm_kernel(const float* __restrict__ Aext, const float* __restrict__ Wext,
                 const float* __restrict__ gamma, const float* __restrict__ beta)
{
    const float* __restrict__ A = AFFINE ? (const float*)g_qx  : Aext;
    const float* __restrict__ W = AFFINE ? (const float*)g_qW2 : Wext;
    float*       __restrict__ C = AFFINE ? (float*)g_h2 : (float*)g_h;

    __shared__ __align__(16) float As[2][16][68];
    __shared__ __align__(16) float Bs[2][16][68];
    __shared__ __align__(16) float sScale[AFFINE ? 512 : 4];
    __shared__ __align__(16) float sShift[AFFINE ? 512 : 4];

    const int tid  = threadIdx.x;
    const int tx   = tid & 15;        // n group (4 cols)
    const int ty   = tid >> 4;        // m group (8 rows)
    const int m0   = blockIdx.y * 64;
    const int n0   = blockIdx.x * 64;
    const int lrow = tid >> 1;        // loader row 0..63
    const int lk   = (tid & 1) * 8;   // loader k half: 0 or 8

    if (AFFINE) {
        for (int c = tid; c < 512; c += 128) {
            float S  = (float)g_bnsum[c];
            float S2 = (float)g_bnsq[c];
            float mu  = S * (1.f / BATCH);
            float var = fmaf(-mu, mu, S2 * (1.f / BATCH));
            float sc  = gamma[c] * rsqrtf(var + 1e-5f);
            sScale[c] = sc;
            sShift[c] = fmaf(-mu, sc, beta[c]);
        }
        __syncthreads();
    } else if (blockIdx.x == 0 && blockIdx.y == 0) {
        // first kernel in the graph: zero all accumulators
        for (int i = tid; i < 512; i += 128) { g_bnsum[i] = 0.0; g_bnsq[i] = 0.0; }
        if (tid < 3) g_dsum[tid] = 0.0;
    }

    constexpr int NT = KDIM / 16;
    float4 pa[2], pb[2];

    // prefetch tile 0
    #pragma unroll
    for (int f = 0; f < 2; f++)
        pa[f] = *(const float4*)(A + (size_t)(m0 + lrow) * KDIM + lk + f * 4);
    #pragma unroll
    for (int f = 0; f < 2; f++)
        pb[f] = *(const float4*)(W + (size_t)(n0 + lrow) * KDIM + lk + f * 4);

    #define STORE_TILE(buf, ktv) do {                                            \
        _Pragma("unroll")                                                        \
        for (int f = 0; f < 2; f++) {                                            \
            float4 av = pa[f];                                                   \
            if (AFFINE) {                                                        \
                float4 sc = *(const float4*)&sScale[(ktv) * 16 + lk + f * 4];    \
                float4 sh = *(const float4*)&sShift[(ktv) * 16 + lk + f * 4];    \
                av.x = fmaf(av.x, sc.x, sh.x);                                   \
                av.y = fmaf(av.y, sc.y, sh.y);                                   \
                av.z = fmaf(av.z, sc.z, sh.z);                                   \
                av.w = fmaf(av.w, sc.w, sh.w);                                   \
            }                                                                    \
            As[buf][lk + f * 4 + 0][lrow] = av.x;                                \
            As[buf][lk + f * 4 + 1][lrow] = av.y;                                \
            As[buf][lk + f * 4 + 2][lrow] = av.z;                                \
            As[buf][lk + f * 4 + 3][lrow] = av.w;                                \
        }                                                                        \
        _Pragma("unroll")                                                        \
        for (int f = 0; f < 2; f++) {                                            \
            float4 bv = pb[f];                                                   \
            Bs[buf][lk + f * 4 + 0][lrow] = bv.x;                                \
            Bs[buf][lk + f * 4 + 1][lrow] = bv.y;                                \
            Bs[buf][lk + f * 4 + 2][lrow] = bv.z;                                \
            Bs[buf][lk + f * 4 + 3][lrow] = bv.w;                                \
        }                                                                        \
    } while (0)

    STORE_TILE(0, 0);
    __syncthreads();

    ull acc[4][4];
    #pragma unroll
    for (int p = 0; p < 4; p++)
        #pragma unroll
        for (int n = 0; n < 4; n++) acc[p][n] = 0ull;

    for (int kt = 0; kt < NT; kt++) {
        const int cur = kt & 1;
        if (kt + 1 < NT) {
            #pragma unroll
            for (int f = 0; f < 2; f++)
                pa[f] = *(const float4*)(A + (size_t)(m0 + lrow) * KDIM
                                         + (kt + 1) * 16 + lk + f * 4);
            #pragma unroll
            for (int f = 0; f < 2; f++)
                pb[f] = *(const float4*)(W + (size_t)(n0 + lrow) * KDIM
                                         + (kt + 1) * 16 + lk + f * 4);
        }
        #pragma unroll
        for (int k = 0; k < 16; k++) {
            // A: 8 m-values = 4 natural ull pairs via two 128-bit loads (broadcast-friendly)
            const ulonglong2 A01 = *(const ulonglong2*)&As[cur][k][ty * 8];
            const ulonglong2 A23 = *(const ulonglong2*)&As[cur][k][ty * 8 + 4];
            const float4 b = *(const float4*)&Bs[cur][k][tx * 4];
            ull ap[4] = { A01.x, A01.y, A23.x, A23.y };
            float bv[4] = { b.x, b.y, b.z, b.w };
            #pragma unroll
            for (int n = 0; n < 4; n++) {
                ull bb = pack2(bv[n], bv[n]);
                acc[0][n] = ffma2(ap[0], bb, acc[0][n]);
                acc[1][n] = ffma2(ap[1], bb, acc[1][n]);
                acc[2][n] = ffma2(ap[2], bb, acc[2][n]);
                acc[3][n] = ffma2(ap[3], bb, acc[3][n]);
            }
        }
        if (kt + 1 < NT) {
            // safe with ONE barrier: this iteration read `cur` only; `cur^1`'s
            // last readers (iteration kt-1) all passed the previous barrier.
            STORE_TILE(cur ^ 1, kt + 1);
            __syncthreads();
        }
    }
    #undef STORE_TILE

    // epilogue: relu + store (rows come in m-pairs)
    #pragma unroll
    for (int p = 0; p < 4; p++) {
        const int r0 = m0 + ty * 8 + 2 * p;
        float2 f0 = unpack2(acc[p][0]);
        float2 f1 = unpack2(acc[p][1]);
        float2 f2 = unpack2(acc[p][2]);
        float2 f3 = unpack2(acc[p][3]);
        float4 o0 = make_float4(fmaxf(f0.x, 0.f), fmaxf(f1.x, 0.f),
                                fmaxf(f2.x, 0.f), fmaxf(f3.x, 0.f));
        float4 o1 = make_float4(fmaxf(f0.y, 0.f), fmaxf(f1.y, 0.f),
                                fmaxf(f2.y, 0.f), fmaxf(f3.y, 0.f));
        *(float4*)(C + (size_t)r0 * 512 + n0 + tx * 4)       = o0;
        *(float4*)(C + (size_t)(r0 + 1) * 512 + n0 + tx * 4) = o1;
    }
}

// ---------------- fq21: dim-8 VQ of h (strided groups) + fused BN stats ----------------
// vector (b,c): v_j = h[b, j*64+c].  4 vectors/thread, 4-code groups, group-min + index recovery.
__global__ __launch_bounds__(256, 2)
void fq21_kernel(const float* __restrict__ E)   // E: [8,512]
{
    __shared__ __align__(16) float sE[8][512];
    __shared__ __align__(16) float sC2[512];
    __shared__ float sBS[4][512];   // per-quadrant column sums
    __shared__ float sBQ[4][512];   // per-quadrant column sq-sums
    const int tid = threadIdx.x;
    for (int i = tid; i < 8 * 512; i += 256) ((float*)sE)[i] = E[i];
    __syncthreads();
    for (int e = tid; e < 512; e += 256) {
        float s = 0.f;
        #pragma unroll
        for (int j = 0; j < 8; j++) s = fmaf(sE[j][e], sE[j][e], s);
        sC2[e] = s;
    }
    __syncthreads();

    const int base = blockIdx.x * 1024 + tid;
    ull vr[4][8];
    #pragma unroll
    for (int s = 0; s < 4; s++) {
        const int vid = base + s * 256;
        const int b = vid >> 6, c = vid & 63;
        #pragma unroll
        for (int j = 0; j < 8; j++) {
            float v = g_h[(size_t)b * 512 + j * 64 + c];
            vr[s][j] = pack2(v, v);
        }
    }

    float bestd[4] = {1e30f, 1e30f, 1e30f, 1e30f};
    int   bg[4]    = {0, 0, 0, 0};
    const ull M2 = pack2(-2.f, -2.f);

    #pragma unroll 2
    for (int u = 0; u < 128; u++) {
        const ull c2A = *(const ull*)&sC2[4 * u];
        const ull c2B = *(const ull*)&sC2[4 * u + 2];
        ull a[4], b2[4];
        {
            const ull eA = *(const ull*)&sE[0][4 * u];
            const ull eB = *(const ull*)&sE[0][4 * u + 2];
            #pragma unroll
            for (int s = 0; s < 4; s++) {
                a [s] = ffma2(vr[s][0], eA, 0ull);
                b2[s] = ffma2(vr[s][0], eB, 0ull);
            }
        }
        #pragma unroll
        for (int j = 1; j < 8; j++) {
            const ull eA = *(const ull*)&sE[j][4 * u];
            const ull eB = *(const ull*)&sE[j][4 * u + 2];
            #pragma unroll
            for (int s = 0; s < 4; s++) {
                a [s] = ffma2(vr[s][j], eA, a [s]);
                b2[s] = ffma2(vr[s][j], eB, b2[s]);
            }
        }
        #pragma unroll
        for (int s = 0; s < 4; s++) {
            float2 fa = unpack2(ffma2(M2, a [s], c2A));
            float2 fb = unpack2(ffma2(M2, b2[s], c2B));
            float m = fminf(fminf(fa.x, fa.y), fminf(fb.x, fb.y));
            if (m < bestd[s]) { bestd[s] = m; bg[s] = u; }
        }
    }

    // index recovery + straight-through write + BN private accumulation
    float priv_s[8], priv_q[8];
    #pragma unroll
    for (int j = 0; j < 8; j++) { priv_s[j] = 0.f; priv_q[j] = 0.f; }
    float lsum = 0.f;
    #pragma unroll
    for (int s = 0; s < 4; s++) {
        const int u = bg[s];
        ull a = 0ull, b2 = 0ull;
        #pragma unroll
        for (int j = 0; j < 8; j++) {
            a  = ffma2(vr[s][j], *(const ull*)&sE[j][4 * u],     a);
            b2 = ffma2(vr[s][j], *(const ull*)&sE[j][4 * u + 2], b2);
        }
        float2 fa = unpack2(ffma2(M2, a,  *(const ull*)&sC2[4 * u]));
        float2 fb = unpack2(ffma2(M2, b2, *(const ull*)&sC2[4 * u + 2]));
        int e = 4 * u;
        if      (fa.x == bestd[s]) e += 0;
        else if (fa.y == bestd[s]) e += 1;
        else if (fb.x == bestd[s]) e += 2;
        else                       e += 3;

        const int vid = base + s * 256;
        const int b = vid >> 6, c = vid & 63;
        #pragma unroll
        for (int j = 0; j < 8; j++) {
            float v  = unpack2(vr[s][j]).x;
            float dq = sE[j][e] - v;
            lsum = fmaf(dq, dq, lsum);
            float qst = v + dq;                      // straight-through value
            g_qx[(size_t)b * 512 + j * 64 + c] = qst;
            priv_s[j] += qst;
            priv_q[j]  = fmaf(qst, qst, priv_q[j]);
        }
    }

    // BN slab reduce: column = j*64 + (tid&63); quadrant q = tid>>6
    {
        const int q = tid >> 6, c = tid & 63;
        #pragma unroll
        for (int j = 0; j < 8; j++) {
            sBS[q][j * 64 + c] = priv_s[j];
            sBQ[q][j * 64 + c] = priv_q[j];
        }
    }
    __syncthreads();
    for (int cell = tid; cell < 512; cell += 256) {
        float s  = sBS[0][cell] + sBS[1][cell] + sBS[2][cell] + sBS[3][cell];
        float s2 = sBQ[0][cell] + sBQ[1][cell] + sBQ[2][cell] + sBQ[3][cell];
        atomicAdd(&g_bnsum[cell], (double)s);
        atomicAdd(&g_bnsq [cell], (double)s2);
    }
    block_sum_to(&g_dsum[0], lsum);
}

// ---------------- weight VQ of W2 (dim-16 groups), 4 threads per vector ----------------
__global__ __launch_bounds__(256)
void wq_kernel(const float* __restrict__ W2, const float* __restrict__ E)
{
    __shared__ __align__(16) float sE[16][512];
    __shared__ __align__(16) float sC2[512];
    const int tid = threadIdx.x;
    for (int i = tid; i < 16 * 512; i += 256) ((float*)sE)[i] = E[i];
    __syncthreads();
    for (int e = tid; e < 512; e += 256) {
        float s = 0.f;
        #pragma unroll
        for (int k = 0; k < 16; k++) s = fmaf(sE[k][e], sE[k][e], s);
        sC2[e] = s;
    }
    __syncthreads();

    const int vec   = blockIdx.x * 64 + (tid >> 2);   // 0..16383
    const int slice = tid & 3;
    const int g = vec >> 6, c = vec & 63;

    ull vr[16];
    #pragma unroll
    for (int k = 0; k < 16; k++) {
        float v = W2[(size_t)(g * 2 + (k & 1)) * 512 + c * 8 + (k >> 1)];
        vr[k] = pack2(v, v);
    }

    float bestd = 1e30f; int bg = slice;
    const ull M2 = pack2(-2.f, -2.f);
    #pragma unroll 2
    for (int uu = 0; uu < 32; uu++) {
        const int u = 4 * uu + slice;
        ull a = 0ull, b2 = 0ull;
        #pragma unroll
        for (int k = 0; k < 16; k++) {
            a  = ffma2(vr[k], *(const ull*)&sE[k][4 * u],     a);
            b2 = ffma2(vr[k], *(const ull*)&sE[k][4 * u + 2], b2);
        }
        float2 fa = unpack2(ffma2(M2, a,  *(const ull*)&sC2[4 * u]));
        float2 fb = unpack2(ffma2(M2, b2, *(const ull*)&sC2[4 * u + 2]));
        float m = fminf(fminf(fa.x, fa.y), fminf(fb.x, fb.y));
        if (m < bestd) { bestd = m; bg = u; }
    }
    int idx;
    {
        ull a = 0ull, b2 = 0ull;
        #pragma unroll
        for (int k = 0; k < 16; k++) {
            a  = ffma2(vr[k], *(const ull*)&sE[k][4 * bg],     a);
            b2 = ffma2(vr[k], *(const ull*)&sE[k][4 * bg + 2], b2);
        }
        float2 fa = unpack2(ffma2(M2, a,  *(const ull*)&sC2[4 * bg]));
        float2 fb = unpack2(ffma2(M2, b2, *(const ull*)&sC2[4 * bg + 2]));
        idx = 4 * bg;
        if      (fa.x == bestd) idx += 0;
        else if (fa.y == bestd) idx += 1;
        else if (fb.x == bestd) idx += 2;
        else                    idx += 3;
    }
    #pragma unroll
    for (int off = 1; off < 4; off <<= 1) {
        float od = __shfl_xor_sync(0xffffffffu, bestd, off);
        int   oi = __shfl_xor_sync(0xffffffffu, idx,   off);
        if (od < bestd || (od == bestd && oi < idx)) { bestd = od; idx = oi; }
    }
    #pragma unroll
    for (int kk = 0; kk < 4; kk++) {
        int k = slice * 4 + kk;
        float v  = unpack2(vr[k]).x;
        float dq = sE[k][idx] - v;
        g_qW2[(size_t)(g * 2 + (k & 1)) * 512 + c * 8 + (k >> 1)] = v + dq;
    }
    float lsum = 0.f;
    if (slice == 0) {
        #pragma unroll
        for (int k = 0; k < 16; k++) {
            float v  = unpack2(vr[k]).x;
            float dq = sE[k][idx] - v;
            lsum = fmaf(dq, dq, lsum);
        }
    }
    block_sum_to(&g_dsum[1], lsum);
}

// ---------------- fq22: dim-2 VQ of h2 (8 vectors per thread) ----------------
// vector (b,c): [h2[b,c], h2[b,256+c]], c in [0,256)
__global__ __launch_bounds__(256)
void fq22_kernel(const float* __restrict__ E)   // E: [2,512]
{
    __shared__ __align__(16) float sm0[512];
    __shared__ __align__(16) float sm1[512];
    __shared__ __align__(16) float sc2[512];
    const int tid = threadIdx.x;
    for (int e = tid; e < 512; e += 256) {
        float e0 = E[e], e1 = E[512 + e];
        sm0[e] = -2.f * e0;
        sm1[e] = -2.f * e1;
        sc2[e] = fmaf(e0, e0, e1 * e1);
    }
    __syncthreads();

    const int base = blockIdx.x * 2048 + tid;
    ull v0r[8], v1r[8];
    #pragma unroll
    for (int s = 0; s < 8; s++) {
        const int vid = base + s * 256;
        const int b = vid >> 8, c = vid & 255;
        float a0 = g_h2[(size_t)b * 512 + c];
        float a1 = g_h2[(size_t)b * 512 + 256 + c];
        v0r[s] = pack2(a0, a0);
        v1r[s] = pack2(a1, a1);
    }
    float bestd[8] = {1e30f, 1e30f, 1e30f, 1e30f, 1e30f, 1e30f, 1e30f, 1e30f};
    int   bg[8]    = {0, 0, 0, 0, 0, 0, 0, 0};
    for (int u = 0; u < 128; u++) {
        const ull m0A = *(const ull*)&sm0[4 * u];
        const ull m0B = *(const ull*)&sm0[4 * u + 2];
        const ull m1A = *(const ull*)&sm1[4 * u];
        const ull m1B = *(const ull*)&sm1[4 * u + 2];
        const ull c2A = *(const ull*)&sc2[4 * u];
        const ull c2B = *(const ull*)&sc2[4 * u + 2];
        #pragma unroll
        for (int s = 0; s < 8; s++) {
            float2 fa = unpack2(ffma2(v0r[s], m0A, ffma2(v1r[s], m1A, c2A)));
            float2 fb = unpack2(ffma2(v0r[s], m0B, ffma2(v1r[s], m1B, c2B)));
            float m = fminf(fminf(fa.x, fa.y), fminf(fb.x, fb.y));
            if (m < bestd[s]) { bestd[s] = m; bg[s] = u; }
        }
    }
    float lsum = 0.f;
    #pragma unroll
    for (int s = 0; s < 8; s++) {
        const int u = bg[s];
        float2 fa = unpack2(ffma2(v0r[s], *(const ull*)&sm0[4 * u],
                      ffma2(v1r[s], *(const ull*)&sm1[4 * u], *(const ull*)&sc2[4 * u])));
        float2 fb = unpack2(ffma2(v0r[s], *(const ull*)&sm0[4 * u + 2],
                      ffma2(v1r[s], *(const ull*)&sm1[4 * u + 2], *(const ull*)&sc2[4 * u + 2])));
        int e = 4 * u;
        if      (fa.x == bestd[s]) e += 0;
        else if (fa.y == bestd[s]) e += 1;
        else if (fb.x == bestd[s]) e += 2;
        else                       e += 3;

        const int vid = base + s * 256;
        const int b = vid >> 8, c = vid & 255;
        float e0 = -0.5f * sm0[e];     // exact recovery of codeword
        float e1 = -0.5f * sm1[e];
        float v0 = unpack2(v0r[s]).x;
        float v1 = unpack2(v1r[s]).x;
        float d0 = e0 - v0, d1 = e1 - v1;
        lsum = fmaf(d0, d0, lsum);
        lsum = fmaf(d1, d1, lsum);
        g_qx2[(size_t)b * 512 + c]       = v0 + d0;
        g_qx2[(size_t)b * 512 + 256 + c] = v1 + d1;
    }
    block_sum_to(&g_dsum[2], lsum);
}

// ---------------- final: out = qx2 @ W3^T, plus diff scalar ----------------
__global__ __launch_bounds__(256)
void out_kernel(const float* __restrict__ W3, float* __restrict__ out, int out_size)
{
    __shared__ float sW3[10 * 512];
    const int tid = threadIdx.x;
    for (int i = tid; i < 5120; i += 256) sW3[i] = W3[i];
    __syncthreads();
    const int lane = tid & 31, warp = tid >> 5;
    const int b = blockIdx.x * 8 + warp;
    float p[10];
    #pragma unroll
    for (int k = 0; k < 10; k++) p[k] = 0.f;
    #pragma unroll
    for (int t = 0; t < 16; t++) {
        const int c = t * 32 + lane;
        float v = g_qx2[(size_t)b * 512 + c];
        #pragma unroll
        for (int k = 0; k < 10; k++) p[k] = fmaf(v, sW3[k * 512 + c], p[k]);
    }
    #pragma unroll
    for (int k = 0; k < 10; k++) {
        #pragma unroll
        for (int o = 16; o; o >>= 1) p[k] += __shfl_xor_sync(0xffffffffu, p[k], o);
    }
    if (lane == 0) {
        #pragma unroll
        for (int k = 0; k < 10; k++) out[b * 10 + k] = p[k];
    }
    if (blockIdx.x == 0 && tid == 0 && out_size > BATCH * 10) {
        double diff = g_dsum[0] * (1.0 / 2097152.0)
                    + g_dsum[2] * (1.0 / 2097152.0)
                    + g_dsum[1] * (1.0 / 262144.0);
        out[BATCH * 10] = (float)diff;
    }
}

// ---------------- launch ----------------
extern "C" void kernel_launch(void* const* d_in, const int* in_sizes, int n_in,
                              void* d_out, int out_size)
{
    const float* x      = (const float*)d_in[0];
    const float* W1     = (const float*)d_in[1];
    const float* W2     = (const float*)d_in[2];
    const float* W3     = (const float*)d_in[3];
    const float* gamma1 = (const float*)d_in[4];
    const float* beta1  = (const float*)d_in[5];
    const float* Ef21   = (const float*)d_in[6];
    const float* Eq2    = (const float*)d_in[7];
    const float* Ef22   = (const float*)d_in[8];
    float* out = (float*)d_out;

    gemm_kernel<784, false><<<dim3(8, 64), 128>>>(x, W1, nullptr, nullptr);        // h = relu(x@W1^T)
    fq21_kernel<<<256, 256>>>(Ef21);                                                // h -> qx (+d_f21, +BN)
    wq_kernel<<<256, 256>>>(W2, Eq2);                                               // W2 -> qW2 (+d2)
    gemm_kernel<512, true><<<dim3(8, 64), 128>>>(nullptr, nullptr, gamma1, beta1);  // h2 = relu(bn(qx)@qW2^T)
    fq22_kernel<<<512, 256>>>(Ef22);                                                // h2 -> qx2 (+d_f22)
    out_kernel<<<512, 256>>>(W3, out, out_size);                                    // logits + diff scalar
}

// round 9
// speedup vs baseline: 1.0454x; 1.0292x over previous
#include <cuda_runtime.h>

typedef unsigned long long ull;

#define BATCH 4096

// ---------------- device scratch (no allocations allowed) ----------------
__device__ float g_h  [BATCH * 512];
__device__ float g_qx [BATCH * 512];
__device__ float g_qW2[512 * 512];
__device__ float g_h2 [BATCH * 512];
__device__ float g_qx2[BATCH * 512];
__device__ double g_bnsum[512];
__device__ double g_bnsq [512];
__device__ double g_dsum[3];   // [0]=fq21 sum, [1]=wq sum, [2]=fq22 sum

// ---------------- packed f32x2 helpers (Blackwell FFMA2) ----------------
__device__ __forceinline__ ull pack2(float x, float y) {
    ull r;
    unsigned xu = __float_as_uint(x), yu = __float_as_uint(y);
    asm("mov.b64 %0, {%1, %2};" : "=l"(r) : "r"(xu), "r"(yu));
    return r;
}
__device__ __forceinline__ float2 unpack2(ull v) {
    unsigned lo, hi;
    asm("mov.b64 {%0, %1}, %2;" : "=r"(lo), "=r"(hi) : "l"(v));
    float2 f; f.x = __uint_as_float(lo); f.y = __uint_as_float(hi);
    return f;
}
__device__ __forceinline__ ull ffma2(ull a, ull b, ull c) {
    ull d;
    asm("fma.rn.f32x2 %0, %1, %2, %3;" : "=l"(d) : "l"(a), "l"(b), "l"(c));
    return d;
}

// ---------------- block reduce -> atomic double ----------------
__device__ __forceinline__ void block_sum_to(double* target, float v) {
    __shared__ float red[8];
    const int tid = threadIdx.x;
    #pragma unroll
    for (int o = 16; o; o >>= 1) v += __shfl_xor_sync(0xffffffffu, v, o);
    if ((tid & 31) == 0) red[tid >> 5] = v;
    __syncthreads();
    if (tid == 0) {
        float s = 0.f;
        const int nw = (blockDim.x + 31) >> 5;
        for (int w = 0; w < nw; w++) s += red[w];
        atomicAdd(target, (double)s);
    }
}

// ---------------- GEMM: C[m,n] = relu( sum_k f(A[m,k]) * W[n,k] ) ----------------
// BM=128, BN=64, BK=16, 256 threads (8 warps).
// Warp-broadcast layout: lanes span m (4 m/lane, dense A LDS), the warp's n
// columns are SHARED by all lanes (B LDS is a broadcast -> 1 wavefront/line).
// Per warp k-step: 6 crossbar wavefronts per 16 FFMA2 (0.375 wf/FFMA2).
// Double-buffered, ONE barrier per k-tile.
// AFFINE: A -> A*scale[k]+shift[k] (fused BN from g_bnsum/g_bnsq).
template<int KDIM, bool AFFINE>
__global__ __launch_bounds__(256, 2)
void gemm_kernel(const float* __restrict__ Aext, const float* __restrict__ Wext,
                 const float* __restrict__ gamma, const float* __restrict__ beta)
{
    const float* __restrict__ A = AFFINE ? (const float*)g_qx  : Aext;
    const float* __restrict__ W = AFFINE ? (const float*)g_qW2 : Wext;
    float*       __restrict__ C = AFFINE ? (float*)g_h2 : (float*)g_h;

    __shared__ __align__(16) float As[2][16][132];
    __shared__ __align__(16) float Bs[2][16][68];
    __shared__ __align__(16) float sScale[AFFINE ? 512 : 4];
    __shared__ __align__(16) float sShift[AFFINE ? 512 : 4];

    const int tid  = threadIdx.x;
    const int w    = tid >> 5;        // warp 0..7 -> n columns w*8..w*8+7
    const int l    = tid & 31;        // lane -> m rows 4l..4l+3
    const int m0   = blockIdx.y * 128;
    const int n0   = blockIdx.x * 64;
    // A loader: row = tid>>1 (0..127), k-half = (tid&1)*8
    const int larow = tid >> 1;
    const int lak   = (tid & 1) * 8;
    // B loader: row = tid>>2 (0..63), k-quad = (tid&3)*4
    const int lbrow = tid >> 2;
    const int lbk   = (tid & 3) * 4;

    if (AFFINE) {
        for (int c = tid; c < 512; c += 256) {
            float S  = (float)g_bnsum[c];
            float S2 = (float)g_bnsq[c];
            float mu  = S * (1.f / BATCH);
            float var = fmaf(-mu, mu, S2 * (1.f / BATCH));
            float sc  = gamma[c] * rsqrtf(var + 1e-5f);
            sScale[c] = sc;
            sShift[c] = fmaf(-mu, sc, beta[c]);
        }
        __syncthreads();
    } else if (blockIdx.x == 0 && blockIdx.y == 0) {
        // first kernel in the graph: zero all accumulators
        for (int i = tid; i < 512; i += 256) { g_bnsum[i] = 0.0; g_bnsq[i] = 0.0; }
        if (tid < 3) g_dsum[tid] = 0.0;
    }

    constexpr int NT = KDIM / 16;
    float4 pa[2], pb;

    // prefetch tile 0
    #pragma unroll
    for (int f = 0; f < 2; f++)
        pa[f] = *(const float4*)(A + (size_t)(m0 + larow) * KDIM + lak + f * 4);
    pb = *(const float4*)(W + (size_t)(n0 + lbrow) * KDIM + lbk);

    #define STORE_TILE(buf, ktv) do {                                            \
        _Pragma("unroll")                                                        \
        for (int f = 0; f < 2; f++) {                                            \
            float4 av = pa[f];                                                   \
            if (AFFINE) {                                                        \
                float4 sc = *(const float4*)&sScale[(ktv) * 16 + lak + f * 4];   \
                float4 sh = *(const float4*)&sShift[(ktv) * 16 + lak + f * 4];   \
                av.x = fmaf(av.x, sc.x, sh.x);                                   \
                av.y = fmaf(av.y, sc.y, sh.y);                                   \
                av.z = fmaf(av.z, sc.z, sh.z);                                   \
                av.w = fmaf(av.w, sc.w, sh.w);                                   \
            }                                                                    \
            As[buf][lak + f * 4 + 0][larow] = av.x;                              \
            As[buf][lak + f * 4 + 1][larow] = av.y;                              \
            As[buf][lak + f * 4 + 2][larow] = av.z;                              \
            As[buf][lak + f * 4 + 3][larow] = av.w;                              \
        }                                                                        \
        Bs[buf][lbk + 0][lbrow] = pb.x;                                          \
        Bs[buf][lbk + 1][lbrow] = pb.y;                                          \
        Bs[buf][lbk + 2][lbrow] = pb.z;                                          \
        Bs[buf][lbk + 3][lbrow] = pb.w;                                          \
    } while (0)

    STORE_TILE(0, 0);
    __syncthreads();

    ull acc[2][8];
    #pragma unroll
    for (int p = 0; p < 2; p++)
        #pragma unroll
        for (int n = 0; n < 8; n++) acc[p][n] = 0ull;

    for (int kt = 0; kt < NT; kt++) {
        const int cur = kt & 1;
        if (kt + 1 < NT) {
            #pragma unroll
            for (int f = 0; f < 2; f++)
                pa[f] = *(const float4*)(A + (size_t)(m0 + larow) * KDIM
                                         + (kt + 1) * 16 + lak + f * 4);
            pb = *(const float4*)(W + (size_t)(n0 + lbrow) * KDIM
                                  + (kt + 1) * 16 + lbk);
        }
        #pragma unroll
        for (int k = 0; k < 16; k++) {
            // A: dense 16B/lane = 4 wavefronts; natural m-pair ulls
            const ulonglong2 Ap = *(const ulonglong2*)&As[cur][k][4 * l];
            // B: all lanes read the warp's 8 columns -> broadcast, 1 wf per line
            const float4 b0 = *(const float4*)&Bs[cur][k][w * 8];
            const float4 b1 = *(const float4*)&Bs[cur][k][w * 8 + 4];
            float bv[8] = { b0.x, b0.y, b0.z, b0.w, b1.x, b1.y, b1.z, b1.w };
            #pragma unroll
            for (int n = 0; n < 8; n++) {
                ull bb = pack2(bv[n], bv[n]);
                acc[0][n] = ffma2(Ap.x, bb, acc[0][n]);
                acc[1][n] = ffma2(Ap.y, bb, acc[1][n]);
            }
        }
        if (kt + 1 < NT) {
            // safe with ONE barrier: this iteration read `cur` only; `cur^1`'s
            // last readers (iteration kt-1) all passed the previous barrier.
            STORE_TILE(cur ^ 1, kt + 1);
            __syncthreads();
        }
    }
    #undef STORE_TILE

    // epilogue: relu + store (m-pairs: rows 4l+2p, 4l+2p+1; cols n0+w*8..+7)
    #pragma unroll
    for (int p = 0; p < 2; p++) {
        const int r0 = m0 + 4 * l + 2 * p;
        float v0[8], v1[8];
        #pragma unroll
        for (int n = 0; n < 8; n++) {
            float2 f = unpack2(acc[p][n]);
            v0[n] = fmaxf(f.x, 0.f);
            v1[n] = fmaxf(f.y, 0.f);
        }
        *(float4*)(C + (size_t)r0 * 512 + n0 + w * 8)           = make_float4(v0[0], v0[1], v0[2], v0[3]);
        *(float4*)(C + (size_t)r0 * 512 + n0 + w * 8 + 4)       = make_float4(v0[4], v0[5], v0[6], v0[7]);
        *(float4*)(C + (size_t)(r0 + 1) * 512 + n0 + w * 8)     = make_float4(v1[0], v1[1], v1[2], v1[3]);
        *(float4*)(C + (size_t)(r0 + 1) * 512 + n0 + w * 8 + 4) = make_float4(v1[4], v1[5], v1[6], v1[7]);
    }
}

// ---------------- fq21: dim-8 VQ of h (strided groups) + fused BN stats ----------------
// vector (b,c): v_j = h[b, j*64+c].  4 vectors/thread, 4-code groups, group-min + index recovery.
__global__ __launch_bounds__(256, 2)
void fq21_kernel(const float* __restrict__ E)   // E: [8,512]
{
    __shared__ __align__(16) float sE[8][512];
    __shared__ __align__(16) float sC2[512];
    __shared__ float sBS[4][512];   // per-quadrant column sums
    __shared__ float sBQ[4][512];   // per-quadrant column sq-sums
    const int tid = threadIdx.x;
    for (int i = tid; i < 8 * 512; i += 256) ((float*)sE)[i] = E[i];
    __syncthreads();
    for (int e = tid; e < 512; e += 256) {
        float s = 0.f;
        #pragma unroll
        for (int j = 0; j < 8; j++) s = fmaf(sE[j][e], sE[j][e], s);
        sC2[e] = s;
    }
    __syncthreads();

    const int base = blockIdx.x * 1024 + tid;
    ull vr[4][8];
    #pragma unroll
    for (int s = 0; s < 4; s++) {
        const int vid = base + s * 256;
        const int b = vid >> 6, c = vid & 63;
        #pragma unroll
        for (int j = 0; j < 8; j++) {
            float v = g_h[(size_t)b * 512 + j * 64 + c];
            vr[s][j] = pack2(v, v);
        }
    }

    float bestd[4] = {1e30f, 1e30f, 1e30f, 1e30f};
    int   bg[4]    = {0, 0, 0, 0};
    const ull M2 = pack2(-2.f, -2.f);

    #pragma unroll 2
    for (int u = 0; u < 128; u++) {
        const ull c2A = *(const ull*)&sC2[4 * u];
        const ull c2B = *(const ull*)&sC2[4 * u + 2];
        ull a[4], b2[4];
        {
            const ull eA = *(const ull*)&sE[0][4 * u];
            const ull eB = *(const ull*)&sE[0][4 * u + 2];
            #pragma unroll
            for (int s = 0; s < 4; s++) {
                a [s] = ffma2(vr[s][0], eA, 0ull);
                b2[s] = ffma2(vr[s][0], eB, 0ull);
            }
        }
        #pragma unroll
        for (int j = 1; j < 8; j++) {
            const ull eA = *(const ull*)&sE[j][4 * u];
            const ull eB = *(const ull*)&sE[j][4 * u + 2];
            #pragma unroll
            for (int s = 0; s < 4; s++) {
                a [s] = ffma2(vr[s][j], eA, a [s]);
                b2[s] = ffma2(vr[s][j], eB, b2[s]);
            }
        }
        #pragma unroll
        for (int s = 0; s < 4; s++) {
            float2 fa = unpack2(ffma2(M2, a [s], c2A));
            float2 fb = unpack2(ffma2(M2, b2[s], c2B));
            float m = fminf(fminf(fa.x, fa.y), fminf(fb.x, fb.y));
            if (m < bestd[s]) { bestd[s] = m; bg[s] = u; }
        }
    }

    // index recovery + straight-through write + BN private accumulation
    float priv_s[8], priv_q[8];
    #pragma unroll
    for (int j = 0; j < 8; j++) { priv_s[j] = 0.f; priv_q[j] = 0.f; }
    float lsum = 0.f;
    #pragma unroll
    for (int s = 0; s < 4; s++) {
        const int u = bg[s];
        ull a = 0ull, b2 = 0ull;
        #pragma unroll
        for (int j = 0; j < 8; j++) {
            a  = ffma2(vr[s][j], *(const ull*)&sE[j][4 * u],     a);
            b2 = ffma2(vr[s][j], *(const ull*)&sE[j][4 * u + 2], b2);
        }
        float2 fa = unpack2(ffma2(M2, a,  *(const ull*)&sC2[4 * u]));
        float2 fb = unpack2(ffma2(M2, b2, *(const ull*)&sC2[4 * u + 2]));
        int e = 4 * u;
        if      (fa.x == bestd[s]) e += 0;
        else if (fa.y == bestd[s]) e += 1;
        else if (fb.x == bestd[s]) e += 2;
        else                       e += 3;

        const int vid = base + s * 256;
        const int b = vid >> 6, c = vid & 63;
        #pragma unroll
        for (int j = 0; j < 8; j++) {
            float v  = unpack2(vr[s][j]).x;
            float dq = sE[j][e] - v;
            lsum = fmaf(dq, dq, lsum);
            float qst = v + dq;                      // straight-through value
            g_qx[(size_t)b * 512 + j * 64 + c] = qst;
            priv_s[j] += qst;
            priv_q[j]  = fmaf(qst, qst, priv_q[j]);
        }
    }

    // BN slab reduce: column = j*64 + (tid&63); quadrant q = tid>>6
    {
        const int q = tid >> 6, c = tid & 63;
        #pragma unroll
        for (int j = 0; j < 8; j++) {
            sBS[q][j * 64 + c] = priv_s[j];
            sBQ[q][j * 64 + c] = priv_q[j];
        }
    }
    __syncthreads();
    for (int cell = tid; cell < 512; cell += 256) {
        float s  = sBS[0][cell] + sBS[1][cell] + sBS[2][cell] + sBS[3][cell];
        float s2 = sBQ[0][cell] + sBQ[1][cell] + sBQ[2][cell] + sBQ[3][cell];
        atomicAdd(&g_bnsum[cell], (double)s);
        atomicAdd(&g_bnsq [cell], (double)s2);
    }
    block_sum_to(&g_dsum[0], lsum);
}

// ---------------- weight VQ of W2 (dim-16 groups), 4 threads per vector ----------------
__global__ __launch_bounds__(256)
void wq_kernel(const float* __restrict__ W2, const float* __restrict__ E)
{
    __shared__ __align__(16) float sE[16][512];
    __shared__ __align__(16) float sC2[512];
    const int tid = threadIdx.x;
    for (int i = tid; i < 16 * 512; i += 256) ((float*)sE)[i] = E[i];
    __syncthreads();
    for (int e = tid; e < 512; e += 256) {
        float s = 0.f;
        #pragma unroll
        for (int k = 0; k < 16; k++) s = fmaf(sE[k][e], sE[k][e], s);
        sC2[e] = s;
    }
    __syncthreads();

    const int vec   = blockIdx.x * 64 + (tid >> 2);   // 0..16383
    const int slice = tid & 3;
    const int g = vec >> 6, c = vec & 63;

    ull vr[16];
    #pragma unroll
    for (int k = 0; k < 16; k++) {
        float v = W2[(size_t)(g * 2 + (k & 1)) * 512 + c * 8 + (k >> 1)];
        vr[k] = pack2(v, v);
    }

    float bestd = 1e30f; int bg = slice;
    const ull M2 = pack2(-2.f, -2.f);
    #pragma unroll 2
    for (int uu = 0; uu < 32; uu++) {
        const int u = 4 * uu + slice;
        ull a = 0ull, b2 = 0ull;
        #pragma unroll
        for (int k = 0; k < 16; k++) {
            a  = ffma2(vr[k], *(const ull*)&sE[k][4 * u],     a);
            b2 = ffma2(vr[k], *(const ull*)&sE[k][4 * u + 2], b2);
        }
        float2 fa = unpack2(ffma2(M2, a,  *(const ull*)&sC2[4 * u]));
        float2 fb = unpack2(ffma2(M2, b2, *(const ull*)&sC2[4 * u + 2]));
        float m = fminf(fminf(fa.x, fa.y), fminf(fb.x, fb.y));
        if (m < bestd) { bestd = m; bg = u; }
    }
    int idx;
    {
        ull a = 0ull, b2 = 0ull;
        #pragma unroll
        for (int k = 0; k < 16; k++) {
            a  = ffma2(vr[k], *(const ull*)&sE[k][4 * bg],     a);
            b2 = ffma2(vr[k], *(const ull*)&sE[k][4 * bg + 2], b2);
        }
        float2 fa = unpack2(ffma2(M2, a,  *(const ull*)&sC2[4 * bg]));
        float2 fb = unpack2(ffma2(M2, b2, *(const ull*)&sC2[4 * bg + 2]));
        idx = 4 * bg;
        if      (fa.x == bestd) idx += 0;
        else if (fa.y == bestd) idx += 1;
        else if (fb.x == bestd) idx += 2;
        else                    idx += 3;
    }
    #pragma unroll
    for (int off = 1; off < 4; off <<= 1) {
        float od = __shfl_xor_sync(0xffffffffu, bestd, off);
        int   oi = __shfl_xor_sync(0xffffffffu, idx,   off);
        if (od < bestd || (od == bestd && oi < idx)) { bestd = od; idx = oi; }
    }
    #pragma unroll
    for (int kk = 0; kk < 4; kk++) {
        int k = slice * 4 + kk;
        float v  = unpack2(vr[k]).x;
        float dq = sE[k][idx] - v;
        g_qW2[(size_t)(g * 2 + (k & 1)) * 512 + c * 8 + (k >> 1)] = v + dq;
    }
    float lsum = 0.f;
    if (slice == 0) {
        #pragma unroll
        for (int k = 0; k < 16; k++) {
            float v  = unpack2(vr[k]).x;
            float dq = sE[k][idx] - v;
            lsum = fmaf(dq, dq, lsum);
        }
    }
    block_sum_to(&g_dsum[1], lsum);
}

// ---------------- fq22: dim-2 VQ of h2 (8 vectors per thread) ----------------
// vector (b,c): [h2[b,c], h2[b,256+c]], c in [0,256)
__global__ __launch_bounds__(256)
void fq22_kernel(const float* __restrict__ E)   // E: [2,512]
{
    __shared__ __align__(16) float sm0[512];
    __shared__ __align__(16) float sm1[512];
    __shared__ __align__(16) float sc2[512];
    const int tid = threadIdx.x;
    for (int e = tid; e < 512; e += 256) {
        float e0 = E[e], e1 = E[512 + e];
        sm0[e] = -2.f * e0;
        sm1[e] = -2.f * e1;
        sc2[e] = fmaf(e0, e0, e1 * e1);
    }
    __syncthreads();

    const int base = blockIdx.x * 2048 + tid;
    ull v0r[8], v1r[8];
    #pragma unroll
    for (int s = 0; s < 8; s++) {
        const int vid = base + s * 256;
        const int b = vid >> 8, c = vid & 255;
        float a0 = g_h2[(size_t)b * 512 + c];
        float a1 = g_h2[(size_t)b * 512 + 256 + c];
        v0r[s] = pack2(a0, a0);
        v1r[s] = pack2(a1, a1);
    }
    float bestd[8] = {1e30f, 1e30f, 1e30f, 1e30f, 1e30f, 1e30f, 1e30f, 1e30f};
    int   bg[8]    = {0, 0, 0, 0, 0, 0, 0, 0};
    for (int u = 0; u < 128; u++) {
        const ull m0A = *(const ull*)&sm0[4 * u];
        const ull m0B = *(const ull*)&sm0[4 * u + 2];
        const ull m1A = *(const ull*)&sm1[4 * u];
        const ull m1B = *(const ull*)&sm1[4 * u + 2];
        const ull c2A = *(const ull*)&sc2[4 * u];
        const ull c2B = *(const ull*)&sc2[4 * u + 2];
        #pragma unroll
        for (int s = 0; s < 8; s++) {
            float2 fa = unpack2(ffma2(v0r[s], m0A, ffma2(v1r[s], m1A, c2A)));
            float2 fb = unpack2(ffma2(v0r[s], m0B, ffma2(v1r[s], m1B, c2B)));
            float m = fminf(fminf(fa.x, fa.y), fminf(fb.x, fb.y));
            if (m < bestd[s]) { bestd[s] = m; bg[s] = u; }
        }
    }
    float lsum = 0.f;
    #pragma unroll
    for (int s = 0; s < 8; s++) {
        const int u = bg[s];
        float2 fa = unpack2(ffma2(v0r[s], *(const ull*)&sm0[4 * u],
                      ffma2(v1r[s], *(const ull*)&sm1[4 * u], *(const ull*)&sc2[4 * u])));
        float2 fb = unpack2(ffma2(v0r[s], *(const ull*)&sm0[4 * u + 2],
                      ffma2(v1r[s], *(const ull*)&sm1[4 * u + 2], *(const ull*)&sc2[4 * u + 2])));
        int e = 4 * u;
        if      (fa.x == bestd[s]) e += 0;
        else if (fa.y == bestd[s]) e += 1;
        else if (fb.x == bestd[s]) e += 2;
        else                       e += 3;

        const int vid = base + s * 256;
        const int b = vid >> 8, c = vid & 255;
        float e0 = -0.5f * sm0[e];     // exact recovery of codeword
        float e1 = -0.5f * sm1[e];
        float v0 = unpack2(v0r[s]).x;
        float v1 = unpack2(v1r[s]).x;
        float d0 = e0 - v0, d1 = e1 - v1;
        lsum = fmaf(d0, d0, lsum);
        lsum = fmaf(d1, d1, lsum);
        g_qx2[(size_t)b * 512 + c]       = v0 + d0;
        g_qx2[(size_t)b * 512 + 256 + c] = v1 + d1;
    }
    block_sum_to(&g_dsum[2], lsum);
}

// ---------------- final: out = qx2 @ W3^T, plus diff scalar ----------------
__global__ __launch_bounds__(256)
void out_kernel(const float* __restrict__ W3, float* __restrict__ out, int out_size)
{
    __shared__ float sW3[10 * 512];
    const int tid = threadIdx.x;
    for (int i = tid; i < 5120; i += 256) sW3[i] = W3[i];
    __syncthreads();
    const int lane = tid & 31, warp = tid >> 5;
    const int b = blockIdx.x * 8 + warp;
    float p[10];
    #pragma unroll
    for (int k = 0; k < 10; k++) p[k] = 0.f;
    #pragma unroll
    for (int t = 0; t < 16; t++) {
        const int c = t * 32 + lane;
        float v = g_qx2[(size_t)b * 512 + c];
        #pragma unroll
        for (int k = 0; k < 10; k++) p[k] = fmaf(v, sW3[k * 512 + c], p[k]);
    }
    #pragma unroll
    for (int k = 0; k < 10; k++) {
        #pragma unroll
        for (int o = 16; o; o >>= 1) p[k] += __shfl_xor_sync(0xffffffffu, p[k], o);
    }
    if (lane == 0) {
        #pragma unroll
        for (int k = 0; k < 10; k++) out[b * 10 + k] = p[k];
    }
    if (blockIdx.x == 0 && tid == 0 && out_size > BATCH * 10) {
        double diff = g_dsum[0] * (1.0 / 2097152.0)
                    + g_dsum[2] * (1.0 / 2097152.0)
                    + g_dsum[1] * (1.0 / 262144.0);
        out[BATCH * 10] = (float)diff;
    }
}

// ---------------- launch ----------------
extern "C" void kernel_launch(void* const* d_in, const int* in_sizes, int n_in,
                              void* d_out, int out_size)
{
    const float* x      = (const float*)d_in[0];
    const float* W1     = (const float*)d_in[1];
    const float* W2     = (const float*)d_in[2];
    const float* W3     = (const float*)d_in[3];
    const float* gamma1 = (const float*)d_in[4];
    const float* beta1  = (const float*)d_in[5];
    const float* Ef21   = (const float*)d_in[6];
    const float* Eq2    = (const float*)d_in[7];
    const float* Ef22   = (const float*)d_in[8];
    float* out = (float*)d_out;

    gemm_kernel<784, false><<<dim3(8, 32), 256>>>(x, W1, nullptr, nullptr);        // h = relu(x@W1^T)
    fq21_kernel<<<256, 256>>>(Ef21);                                                // h -> qx (+d_f21, +BN)
    wq_kernel<<<256, 256>>>(W2, Eq2);                                               // W2 -> qW2 (+d2)
    gemm_kernel<512, true><<<dim3(8, 32), 256>>>(nullptr, nullptr, gamma1, beta1);  // h2 = relu(bn(qx)@qW2^T)
    fq22_kernel<<<512, 256>>>(Ef22);                                                // h2 -> qx2 (+d_f22)
    out_kernel<<<512, 256>>>(W3, out, out_size);                                    // logits + diff scalar
}

// round 10
// speedup vs baseline: 1.0588x; 1.0128x over previous
#include <cuda_runtime.h>

typedef unsigned long long ull;

#define BATCH 4096

// ---------------- device scratch (no allocations allowed) ----------------
__device__ float g_xT  [784 * BATCH];   // x transposed [k][m]
__device__ float g_W1T [784 * 512];     // W1 transposed [k][n]
__device__ float g_h   [BATCH * 512];   // relu(x@W1^T), row-major [m][n]
__device__ float g_qxT [512 * BATCH];   // quantized h, TRANSPOSED [k][m]
__device__ float g_qW2T[512 * 512];     // quantized W2, TRANSPOSED [k][n]
__device__ float g_h2  [BATCH * 512];
__device__ float g_qx2 [BATCH * 512];
__device__ double g_bnsum[512];
__device__ double g_bnsq [512];
__device__ double g_dsum[3];   // [0]=fq21 sum, [1]=wq sum, [2]=fq22 sum

// ---------------- packed f32x2 helpers (Blackwell FFMA2) ----------------
__device__ __forceinline__ ull pack2(float x, float y) {
    ull r;
    unsigned xu = __float_as_uint(x), yu = __float_as_uint(y);
    asm("mov.b64 %0, {%1, %2};" : "=l"(r) : "r"(xu), "r"(yu));
    return r;
}
__device__ __forceinline__ float2 unpack2(ull v) {
    unsigned lo, hi;
    asm("mov.b64 {%0, %1}, %2;" : "=r"(lo), "=r"(hi) : "l"(v));
    float2 f; f.x = __uint_as_float(lo); f.y = __uint_as_float(hi);
    return f;
}
__device__ __forceinline__ ull ffma2(ull a, ull b, ull c) {
    ull d;
    asm("fma.rn.f32x2 %0, %1, %2, %3;" : "=l"(d) : "l"(a), "l"(b), "l"(c));
    return d;
}

// ---------------- block reduce -> atomic double ----------------
__device__ __forceinline__ void block_sum_to(double* target, float v) {
    __shared__ float red[8];
    const int tid = threadIdx.x;
    #pragma unroll
    for (int o = 16; o; o >>= 1) v += __shfl_xor_sync(0xffffffffu, v, o);
    if ((tid & 31) == 0) red[tid >> 5] = v;
    __syncthreads();
    if (tid == 0) {
        float s = 0.f;
        const int nw = (blockDim.x + 31) >> 5;
        for (int w = 0; w < nw; w++) s += red[w];
        atomicAdd(target, (double)s);
    }
}

// ---------------- tiled transpose: in[R][C] -> out[C][R] ----------------
__global__ void transpose_kernel(const float* __restrict__ in, float* __restrict__ out,
                                 int R, int C, int zero_flag)
{
    __shared__ float t[32][33];
    const int cx = blockIdx.x * 32, ry = blockIdx.y * 32;
    if (zero_flag && blockIdx.x == 0 && blockIdx.y == 0) {
        int tid = threadIdx.y * 32 + threadIdx.x;
        for (int i = tid; i < 512; i += 256) { g_bnsum[i] = 0.0; g_bnsq[i] = 0.0; }
        if (tid < 3) g_dsum[tid] = 0.0;
    }
    #pragma unroll
    for (int j = threadIdx.y; j < 32; j += 8) {
        int r = ry + j, c = cx + threadIdx.x;
        t[j][threadIdx.x] = (r < R && c < C) ? in[(size_t)r * C + c] : 0.f;
    }
    __syncthreads();
    #pragma unroll
    for (int j = threadIdx.y; j < 32; j += 8) {
        int c = cx + j, r = ry + threadIdx.x;
        if (c < C && r < R) out[(size_t)c * R + r] = t[threadIdx.x][j];
    }
}

// ---------------- GEMM: C[m,n] = relu( sum_k f(A[k,m]) * B[k,n] ) ----------------
// BOTH operands k-major in GMEM -> coalesced LDG.128 + vector STS.128, no transpose.
// BM=128, BN=64, BK=16, 128 threads (4 warps).
// Warp layout: half-warp n-split. lane l: h=l>>4, i=l&15; rows {4i..4i+3, 64+4i..+3},
// cols n0 + w*16 + h*8 .. +7.  Per warp per k: A 4 wf (halves dedup) + B 2 wf
// per 32 FFMA2.  Double-buffered, ONE barrier per k-tile.
// AFFINE: A row k scaled by scale[k], shifted by shift[k] (fused BN).
template<int KDIM, bool AFFINE>
__global__ __launch_bounds__(128, 3)
void gemm_kernel(const float* __restrict__ Aext, const float* __restrict__ Bext,
                 float* __restrict__ Cext,
                 const float* __restrict__ gamma, const float* __restrict__ beta)
{
    const float* __restrict__ A = AFFINE ? (const float*)g_qxT  : Aext;
    const float* __restrict__ B = AFFINE ? (const float*)g_qW2T : Bext;
    float*       __restrict__ C = AFFINE ? (float*)g_h2 : Cext;

    __shared__ __align__(16) float As[2][16][128];
    __shared__ __align__(16) float Bs[2][16][64];
    __shared__ __align__(16) float sScale[AFFINE ? 512 : 4];
    __shared__ __align__(16) float sShift[AFFINE ? 512 : 4];

    const int tid = threadIdx.x;
    const int w   = tid >> 5;          // warp 0..3
    const int l   = tid & 31;
    const int h   = l >> 4;            // half-warp
    const int i   = l & 15;
    const int nb  = w * 16 + h * 8;    // warp/half n columns (8)
    const int m0  = blockIdx.y * 128;
    const int n0  = blockIdx.x * 64;
    const int akr = tid >> 3;          // loader k-row 0..15
    const int acs = (tid & 7) * 4;     // loader col start (+f*32)

    if (AFFINE) {
        for (int c = tid; c < 512; c += 128) {
            float S  = (float)g_bnsum[c];
            float S2 = (float)g_bnsq[c];
            float mu  = S * (1.f / BATCH);
            float var = fmaf(-mu, mu, S2 * (1.f / BATCH));
            float sc  = gamma[c] * rsqrtf(var + 1e-5f);
            sScale[c] = sc;
            sShift[c] = fmaf(-mu, sc, beta[c]);
        }
        __syncthreads();
    }

    constexpr int NT = KDIM / 16;
    float4 pa[4], pb[2];

    // prefetch tile 0 (coalesced: 8 lanes x 16B contiguous per k-row)
    #pragma unroll
    for (int f = 0; f < 4; f++)
        pa[f] = *(const float4*)(A + (size_t)akr * BATCH + m0 + acs + f * 32);
    #pragma unroll
    for (int f = 0; f < 2; f++)
        pb[f] = *(const float4*)(B + (size_t)akr * 512 + n0 + acs + f * 32);

    #define STORE_TILE(buf, ktv) do {                                            \
        float _sc = 1.f, _sh = 0.f;                                              \
        if (AFFINE) { _sc = sScale[(ktv) * 16 + akr]; _sh = sShift[(ktv) * 16 + akr]; } \
        _Pragma("unroll")                                                        \
        for (int f = 0; f < 4; f++) {                                            \
            float4 av = pa[f];                                                   \
            if (AFFINE) {                                                        \
                av.x = fmaf(av.x, _sc, _sh);                                     \
                av.y = fmaf(av.y, _sc, _sh);                                     \
                av.z = fmaf(av.z, _sc, _sh);                                     \
                av.w = fmaf(av.w, _sc, _sh);                                     \
            }                                                                    \
            *(float4*)&As[buf][akr][acs + f * 32] = av;                          \
        }                                                                        \
        _Pragma("unroll")                                                        \
        for (int f = 0; f < 2; f++)                                              \
            *(float4*)&Bs[buf][akr][acs + f * 32] = pb[f];                       \
    } while (0)

    STORE_TILE(0, 0);
    __syncthreads();

    ull acc[4][8];
    #pragma unroll
    for (int p = 0; p < 4; p++)
        #pragma unroll
        for (int n = 0; n < 8; n++) acc[p][n] = 0ull;

    for (int kt = 0; kt < NT; kt++) {
        const int cur = kt & 1;
        if (kt + 1 < NT) {
            #pragma unroll
            for (int f = 0; f < 4; f++)
                pa[f] = *(const float4*)(A + (size_t)((kt + 1) * 16 + akr) * BATCH
                                         + m0 + acs + f * 32);
            #pragma unroll
            for (int f = 0; f < 2; f++)
                pb[f] = *(const float4*)(B + (size_t)((kt + 1) * 16 + akr) * 512
                                         + n0 + acs + f * 32);
        }
        #pragma unroll
        for (int k = 0; k < 16; k++) {
            // A: rows 4i..4i+3 and 64+4i..+3 as natural ull pairs; halves dedup
            const ulonglong2 A0 = *(const ulonglong2*)&As[cur][k][4 * i];
            const ulonglong2 A1 = *(const ulonglong2*)&As[cur][k][64 + 4 * i];
            // B: 8 cols shared by the half-warp -> broadcast wavefronts
            const float4 b0 = *(const float4*)&Bs[cur][k][nb];
            const float4 b1 = *(const float4*)&Bs[cur][k][nb + 4];
            ull ap[4] = { A0.x, A0.y, A1.x, A1.y };
            float bv[8] = { b0.x, b0.y, b0.z, b0.w, b1.x, b1.y, b1.z, b1.w };
            #pragma unroll
            for (int n = 0; n < 8; n++) {
                ull bb = pack2(bv[n], bv[n]);
                acc[0][n] = ffma2(ap[0], bb, acc[0][n]);
                acc[1][n] = ffma2(ap[1], bb, acc[1][n]);
                acc[2][n] = ffma2(ap[2], bb, acc[2][n]);
                acc[3][n] = ffma2(ap[3], bb, acc[3][n]);
            }
        }
        if (kt + 1 < NT) {
            // one barrier: this iter read `cur`; `cur^1`'s last readers passed prev barrier
            STORE_TILE(cur ^ 1, kt + 1);
            __syncthreads();
        }
    }
    #undef STORE_TILE

    // epilogue: relu + store (row-major C)
    #pragma unroll
    for (int p = 0; p < 4; p++) {
        const int r0 = m0 + (p < 2 ? 4 * i + 2 * p : 64 + 4 * i + 2 * (p - 2));
        float v0[8], v1[8];
        #pragma unroll
        for (int n = 0; n < 8; n++) {
            float2 f = unpack2(acc[p][n]);
            v0[n] = fmaxf(f.x, 0.f);
            v1[n] = fmaxf(f.y, 0.f);
        }
        *(float4*)(C + (size_t)r0 * 512 + n0 + nb)           = make_float4(v0[0], v0[1], v0[2], v0[3]);
        *(float4*)(C + (size_t)r0 * 512 + n0 + nb + 4)       = make_float4(v0[4], v0[5], v0[6], v0[7]);
        *(float4*)(C + (size_t)(r0 + 1) * 512 + n0 + nb)     = make_float4(v1[0], v1[1], v1[2], v1[3]);
        *(float4*)(C + (size_t)(r0 + 1) * 512 + n0 + nb + 4) = make_float4(v1[4], v1[5], v1[6], v1[7]);
    }
}

// ---------------- fq21: dim-8 VQ of h + fused BN stats, TRANSPOSED output ----------------
// vector (b,c): v_j = h[b, j*64+c]. Block covers 16 batches x 64 c (all 512 channels).
// Stages quantized values in smem, drains BN sums + k-major g_qxT from the stage.
__global__ __launch_bounds__(256, 2)
void fq21_kernel(const float* __restrict__ E)   // E: [8,512]
{
    __shared__ __align__(16) float sE[8][512];
    __shared__ __align__(16) float sC2[512];
    __shared__ float sT[256][17];     // half of the 512ch x 16b tile, padded
    const int tid = threadIdx.x;
    for (int idx = tid; idx < 8 * 512; idx += 256) ((float*)sE)[idx] = E[idx];
    __syncthreads();
    for (int e = tid; e < 512; e += 256) {
        float s = 0.f;
        #pragma unroll
        for (int j = 0; j < 8; j++) s = fmaf(sE[j][e], sE[j][e], s);
        sC2[e] = s;
    }
    __syncthreads();

    const int base = blockIdx.x * 1024 + tid;
    ull vr[4][8];
    #pragma unroll
    for (int s = 0; s < 4; s++) {
        const int vid = base + s * 256;
        const int b = vid >> 6, c = vid & 63;
        #pragma unroll
        for (int j = 0; j < 8; j++) {
            float v = g_h[(size_t)b * 512 + j * 64 + c];
            vr[s][j] = pack2(v, v);
        }
    }

    float bestd[4] = {1e30f, 1e30f, 1e30f, 1e30f};
    int   bg[4]    = {0, 0, 0, 0};
    const ull M2 = pack2(-2.f, -2.f);

    #pragma unroll 2
    for (int u = 0; u < 128; u++) {
        const ull c2A = *(const ull*)&sC2[4 * u];
        const ull c2B = *(const ull*)&sC2[4 * u + 2];
        ull a[4], b2[4];
        {
            const ull eA = *(const ull*)&sE[0][4 * u];
            const ull eB = *(const ull*)&sE[0][4 * u + 2];
            #pragma unroll
            for (int s = 0; s < 4; s++) {
                a [s] = ffma2(vr[s][0], eA, 0ull);
                b2[s] = ffma2(vr[s][0], eB, 0ull);
            }
        }
        #pragma unroll
        for (int j = 1; j < 8; j++) {
            const ull eA = *(const ull*)&sE[j][4 * u];
            const ull eB = *(const ull*)&sE[j][4 * u + 2];
            #pragma unroll
            for (int s = 0; s < 4; s++) {
                a [s] = ffma2(vr[s][j], eA, a [s]);
                b2[s] = ffma2(vr[s][j], eB, b2[s]);
            }
        }
        #pragma unroll
        for (int s = 0; s < 4; s++) {
            float2 fa = unpack2(ffma2(M2, a [s], c2A));
            float2 fb = unpack2(ffma2(M2, b2[s], c2B));
            float m = fminf(fminf(fa.x, fa.y), fminf(fb.x, fb.y));
            if (m < bestd[s]) { bestd[s] = m; bg[s] = u; }
        }
    }

    // index recovery -> straight-through values qv[s][j]
    float qv[4][8];
    float lsum = 0.f;
    #pragma unroll
    for (int s = 0; s < 4; s++) {
        const int u = bg[s];
        ull a = 0ull, b2 = 0ull;
        #pragma unroll
        for (int j = 0; j < 8; j++) {
            a  = ffma2(vr[s][j], *(const ull*)&sE[j][4 * u],     a);
            b2 = ffma2(vr[s][j], *(const ull*)&sE[j][4 * u + 2], b2);
        }
        float2 fa = unpack2(ffma2(M2, a,  *(const ull*)&sC2[4 * u]));
        float2 fb = unpack2(ffma2(M2, b2, *(const ull*)&sC2[4 * u + 2]));
        int e = 4 * u;
        if      (fa.x == bestd[s]) e += 0;
        else if (fa.y == bestd[s]) e += 1;
        else if (fb.x == bestd[s]) e += 2;
        else                       e += 3;
        #pragma unroll
        for (int j = 0; j < 8; j++) {
            float v  = unpack2(vr[s][j]).x;
            float dq = sE[j][e] - v;
            lsum = fmaf(dq, dq, lsum);
            qv[s][j] = v + dq;
        }
    }

    // stage + drain two 256-channel halves
    const int c  = tid & 63;
    const int b0 = blockIdx.x * 16;
    #pragma unroll
    for (int half = 0; half < 2; half++) {
        __syncthreads();
        #pragma unroll
        for (int s = 0; s < 4; s++) {
            const int bl = s * 4 + (tid >> 6);
            #pragma unroll
            for (int j2 = 0; j2 < 4; j2++)
                sT[j2 * 64 + c][bl] = qv[s][half * 4 + j2];
        }
        __syncthreads();
        // BN sums: one channel-row per thread
        {
            const int ch = half * 256 + tid;
            float s1 = 0.f, s2 = 0.f;
            #pragma unroll
            for (int bl = 0; bl < 16; bl++) {
                float v = sT[tid][bl];
                s1 += v;
                s2 = fmaf(v, v, s2);
            }
            atomicAdd(&g_bnsum[ch], (double)s1);
            atomicAdd(&g_bnsq [ch], (double)s2);
        }
        // qxT write: 4 threads per row, 16B each (64B/row fully-used sectors)
        {
            const int quad = tid & 3;
            #pragma unroll
            for (int p = 0; p < 4; p++) {
                const int row = p * 64 + (tid >> 2);
                float4 v = make_float4(sT[row][quad * 4 + 0], sT[row][quad * 4 + 1],
                                       sT[row][quad * 4 + 2], sT[row][quad * 4 + 3]);
                *(float4*)(g_qxT + (size_t)(half * 256 + row) * BATCH + b0 + quad * 4) = v;
            }
        }
    }
    block_sum_to(&g_dsum[0], lsum);
}

// ---------------- weight VQ of W2 (dim-16 groups), TRANSPOSED output ----------------
__global__ __launch_bounds__(256)
void wq_kernel(const float* __restrict__ W2, const float* __restrict__ E)
{
    __shared__ __align__(16) float sE[16][512];
    __shared__ __align__(16) float sC2[512];
    const int tid = threadIdx.x;
    for (int i = tid; i < 16 * 512; i += 256) ((float*)sE)[i] = E[i];
    __syncthreads();
    for (int e = tid; e < 512; e += 256) {
        float s = 0.f;
        #pragma unroll
        for (int k = 0; k < 16; k++) s = fmaf(sE[k][e], sE[k][e], s);
        sC2[e] = s;
    }
    __syncthreads();

    const int vec   = blockIdx.x * 64 + (tid >> 2);   // 0..16383
    const int slice = tid & 3;
    const int g = vec >> 6, c = vec & 63;

    ull vr[16];
    #pragma unroll
    for (int k = 0; k < 16; k++) {
        float v = W2[(size_t)(g * 2 + (k & 1)) * 512 + c * 8 + (k >> 1)];
        vr[k] = pack2(v, v);
    }

    float bestd = 1e30f; int bg = slice;
    const ull M2 = pack2(-2.f, -2.f);
    #pragma unroll 2
    for (int uu = 0; uu < 32; uu++) {
        const int u = 4 * uu + slice;
        ull a = 0ull, b2 = 0ull;
        #pragma unroll
        for (int k = 0; k < 16; k++) {
            a  = ffma2(vr[k], *(const ull*)&sE[k][4 * u],     a);
            b2 = ffma2(vr[k], *(const ull*)&sE[k][4 * u + 2], b2);
        }
        float2 fa = unpack2(ffma2(M2, a,  *(const ull*)&sC2[4 * u]));
        float2 fb = unpack2(ffma2(M2, b2, *(const ull*)&sC2[4 * u + 2]));
        float m = fminf(fminf(fa.x, fa.y), fminf(fb.x, fb.y));
        if (m < bestd) { bestd = m; bg = u; }
    }
    int idx;
    {
        ull a = 0ull, b2 = 0ull;
        #pragma unroll
        for (int k = 0; k < 16; k++) {
            a  = ffma2(vr[k], *(const ull*)&sE[k][4 * bg],     a);
            b2 = ffma2(vr[k], *(const ull*)&sE[k][4 * bg + 2], b2);
        }
        float2 fa = unpack2(ffma2(M2, a,  *(const ull*)&sC2[4 * bg]));
        float2 fb = unpack2(ffma2(M2, b2, *(const ull*)&sC2[4 * bg + 2]));
        idx = 4 * bg;
        if      (fa.x == bestd) idx += 0;
        else if (fa.y == bestd) idx += 1;
        else if (fb.x == bestd) idx += 2;
        else                    idx += 3;
    }
    #pragma unroll
    for (int off = 1; off < 4; off <<= 1) {
        float od = __shfl_xor_sync(0xffffffffu, bestd, off);
        int   oi = __shfl_xor_sync(0xffffffffu, idx,   off);
        if (od < bestd || (od == bestd && oi < idx)) { bestd = od; idx = oi; }
    }
    // transposed scatter: qW2T[kk][n] with kk = c*8+(k>>1), n = g*2+(k&1)
    #pragma unroll
    for (int kk = 0; kk < 4; kk++) {
        int k = slice * 4 + kk;
        float v  = unpack2(vr[k]).x;
        float dq = sE[k][idx] - v;
        g_qW2T[(size_t)(c * 8 + (k >> 1)) * 512 + g * 2 + (k & 1)] = v + dq;
    }
    float lsum = 0.f;
    if (slice == 0) {
        #pragma unroll
        for (int k = 0; k < 16; k++) {
            float v  = unpack2(vr[k]).x;
            float dq = sE[k][idx] - v;
            lsum = fmaf(dq, dq, lsum);
        }
    }
    block_sum_to(&g_dsum[1], lsum);
}

// ---------------- fq22: dim-2 VQ of h2 (8 vectors per thread) ----------------
__global__ __launch_bounds__(256)
void fq22_kernel(const float* __restrict__ E)   // E: [2,512]
{
    __shared__ __align__(16) float sm0[512];
    __shared__ __align__(16) float sm1[512];
    __shared__ __align__(16) float sc2[512];
    const int tid = threadIdx.x;
    for (int e = tid; e < 512; e += 256) {
        float e0 = E[e], e1 = E[512 + e];
        sm0[e] = -2.f * e0;
        sm1[e] = -2.f * e1;
        sc2[e] = fmaf(e0, e0, e1 * e1);
    }
    __syncthreads();

    const int base = blockIdx.x * 2048 + tid;
    ull v0r[8], v1r[8];
    #pragma unroll
    for (int s = 0; s < 8; s++) {
        const int vid = base + s * 256;
        const int b = vid >> 8, c = vid & 255;
        float a0 = g_h2[(size_t)b * 512 + c];
        float a1 = g_h2[(size_t)b * 512 + 256 + c];
        v0r[s] = pack2(a0, a0);
        v1r[s] = pack2(a1, a1);
    }
    float bestd[8] = {1e30f, 1e30f, 1e30f, 1e30f, 1e30f, 1e30f, 1e30f, 1e30f};
    int   bg[8]    = {0, 0, 0, 0, 0, 0, 0, 0};
    for (int u = 0; u < 128; u++) {
        const ull m0A = *(const ull*)&sm0[4 * u];
        const ull m0B = *(const ull*)&sm0[4 * u + 2];
        const ull m1A = *(const ull*)&sm1[4 * u];
        const ull m1B = *(const ull*)&sm1[4 * u + 2];
        const ull c2A = *(const ull*)&sc2[4 * u];
        const ull c2B = *(const ull*)&sc2[4 * u + 2];
        #pragma unroll
        for (int s = 0; s < 8; s++) {
            float2 fa = unpack2(ffma2(v0r[s], m0A, ffma2(v1r[s], m1A, c2A)));
            float2 fb = unpack2(ffma2(v0r[s], m0B, ffma2(v1r[s], m1B, c2B)));
            float m = fminf(fminf(fa.x, fa.y), fminf(fb.x, fb.y));
            if (m < bestd[s]) { bestd[s] = m; bg[s] = u; }
        }
    }
    float lsum = 0.f;
    #pragma unroll
    for (int s = 0; s < 8; s++) {
        const int u = bg[s];
        float2 fa = unpack2(ffma2(v0r[s], *(const ull*)&sm0[4 * u],
                      ffma2(v1r[s], *(const ull*)&sm1[4 * u], *(const ull*)&sc2[4 * u])));
        float2 fb = unpack2(ffma2(v0r[s], *(const ull*)&sm0[4 * u + 2],
                      ffma2(v1r[s], *(const ull*)&sm1[4 * u + 2], *(const ull*)&sc2[4 * u + 2])));
        int e = 4 * u;
        if      (fa.x == bestd[s]) e += 0;
        else if (fa.y == bestd[s]) e += 1;
        else if (fb.x == bestd[s]) e += 2;
        else                       e += 3;

        const int vid = base + s * 256;
        const int b = vid >> 8, c = vid & 255;
        float e0 = -0.5f * sm0[e];     // exact recovery of codeword
        float e1 = -0.5f * sm1[e];
        float v0 = unpack2(v0r[s]).x;
        float v1 = unpack2(v1r[s]).x;
        float d0 = e0 - v0, d1 = e1 - v1;
        lsum = fmaf(d0, d0, lsum);
        lsum = fmaf(d1, d1, lsum);
        g_qx2[(size_t)b * 512 + c]       = v0 + d0;
        g_qx2[(size_t)b * 512 + 256 + c] = v1 + d1;
    }
    block_sum_to(&g_dsum[2], lsum);
}

// ---------------- final: out = qx2 @ W3^T, plus diff scalar ----------------
__global__ __launch_bounds__(256)
void out_kernel(const float* __restrict__ W3, float* __restrict__ out, int out_size)
{
    __shared__ float sW3[10 * 512];
    const int tid = threadIdx.x;
    for (int i = tid; i < 5120; i += 256) sW3[i] = W3[i];
    __syncthreads();
    const int lane = tid & 31, warp = tid >> 5;
    const int b = blockIdx.x * 8 + warp;
    float p[10];
    #pragma unroll
    for (int k = 0; k < 10; k++) p[k] = 0.f;
    #pragma unroll
    for (int t = 0; t < 16; t++) {
        const int c = t * 32 + lane;
        float v = g_qx2[(size_t)b * 512 + c];
        #pragma unroll
        for (int k = 0; k < 10; k++) p[k] = fmaf(v, sW3[k * 512 + c], p[k]);
    }
    #pragma unroll
    for (int k = 0; k < 10; k++) {
        #pragma unroll
        for (int o = 16; o; o >>= 1) p[k] += __shfl_xor_sync(0xffffffffu, p[k], o);
    }
    if (lane == 0) {
        #pragma unroll
        for (int k = 0; k < 10; k++) out[b * 10 + k] = p[k];
    }
    if (blockIdx.x == 0 && tid == 0 && out_size > BATCH * 10) {
        double diff = g_dsum[0] * (1.0 / 2097152.0)
                    + g_dsum[2] * (1.0 / 2097152.0)
                    + g_dsum[1] * (1.0 / 262144.0);
        out[BATCH * 10] = (float)diff;
    }
}

// ---------------- launch ----------------
extern "C" void kernel_launch(void* const* d_in, const int* in_sizes, int n_in,
                              void* d_out, int out_size)
{
    const float* x      = (const float*)d_in[0];
    const float* W1     = (const float*)d_in[1];
    const float* W2     = (const float*)d_in[2];
    const float* W3     = (const float*)d_in[3];
    const float* gamma1 = (const float*)d_in[4];
    const float* beta1  = (const float*)d_in[5];
    const float* Ef21   = (const float*)d_in[6];
    const float* Eq2    = (const float*)d_in[7];
    const float* Ef22   = (const float*)d_in[8];
    float* out = (float*)d_out;

    float* xT;   cudaGetSymbolAddress((void**)&xT,   g_xT);
    float* W1T;  cudaGetSymbolAddress((void**)&W1T,  g_W1T);
    float* h;    cudaGetSymbolAddress((void**)&h,    g_h);

    transpose_kernel<<<dim3(25, 128), dim3(32, 8)>>>(x,  xT,  4096, 784, 1);  // x -> xT, zero accums
    transpose_kernel<<<dim3(25, 16),  dim3(32, 8)>>>(W1, W1T, 512,  784, 0);  // W1 -> W1T
    gemm_kernel<784, false><<<dim3(8, 32), 128>>>(xT, W1T, h, nullptr, nullptr);    // h = relu(x@W1^T)
    fq21_kernel<<<256, 256>>>(Ef21);                                                 // h -> qxT (+d_f21, +BN)
    wq_kernel<<<256, 256>>>(W2, Eq2);                                                // W2 -> qW2T (+d2)
    gemm_kernel<512, true><<<dim3(8, 32), 128>>>(nullptr, nullptr, nullptr, gamma1, beta1); // h2
    fq22_kernel<<<512, 256>>>(Ef22);                                                 // h2 -> qx2 (+d_f22)
    out_kernel<<<512, 256>>>(W3, out, out_size);                                     // logits + diff scalar
}